// round 3
// baseline (speedup 1.0000x reference)
#include <cuda_runtime.h>
#include <math.h>

// Problem constants (from reference setup: V=8192, F=256, B=32, L=64)
#define VV     8192
#define FF     256
#define BBATCH 32
#define LLEN   64
#define RR     2016      // B*(L-1) rows
#define RPAD   2048      // padded to multiple of BM
#define BM     128
#define BN     128
#define KC     32
#define NT     (VV / BN)    // 64 v-tiles
#define MT     (RPAD / BM)  // 16 m-tiles
#define VMASK  (VV - 1)

struct Cfg { float w0, W, w0x2, thresh; int flag; int sstride; };

__device__ Cfg   g_cfg;
__device__ float g_Bf[VV * FF];        // features as f32 (8 MB)
__device__ float g_A[RPAD * FF];       // wf * feat[u] per row (2 MB)
__device__ float g_sfeat[VV];          // feat[v] . wf
__device__ float g_rowbias[RPAD];      // w0*(W - s_u)
__device__ int   g_tgt[RPAD];
__device__ float g_pm[RPAD * NT];      // partial max per (row, v-tile)
__device__ float g_ps[RPAD * NT];      // partial sum per (row, v-tile)

__device__ __forceinline__ float neg_inf() { return __int_as_float(0xff800000u); }

// ---------------------------------------------------------------------------
// P0: scalars — W = sum(wf), flag = (w0>=0 && all wf>=0), threshold,
//     and sequence dtype detection (int32 vs int64) by scanning odd words.
// ---------------------------------------------------------------------------
__global__ void k_p0(const float* __restrict__ w, const int* __restrict__ seq32) {
    int tid = threadIdx.x;                    // 256 threads, f = tid
    float wf = w[1 + tid];
    float s = wf, mn = wf;
    #pragma unroll
    for (int o = 16; o; o >>= 1) {
        s += __shfl_down_sync(0xffffffffu, s, o);
        float m2 = __shfl_down_sync(0xffffffffu, mn, o);
        mn = fminf(mn, m2);
    }
    __shared__ float ssum[8], smin[8];
    if ((tid & 31) == 0) { ssum[tid >> 5] = s; smin[tid >> 5] = mn; }
    __syncthreads();
    if (tid == 0) {
        float S = 0.f, M = 3.0e38f;
        #pragma unroll
        for (int i = 0; i < 8; i++) { S += ssum[i]; M = fminf(M, smin[i]); }
        float w0 = w[0];
        Cfg c;
        c.w0 = w0; c.W = S; c.w0x2 = 2.0f * w0;
        c.flag = (w0 >= 0.f && M >= 0.f) ? 1 : 0;   // max logit provably = w0*W (attained at v=u)
        c.thresh = w0 * S - 33.0f;
        // dtype sniff: little-endian int64 values < 2^31 have all odd 32-bit
        // words == 0; random int32 vocab ids (< 8192) essentially never do.
        int is64 = 1;
        for (int i = 0; i < 32; i++) {
            if (seq32[2 * i + 1] != 0) { is64 = 0; break; }
        }
        c.sstride = is64 ? 2 : 1;
        g_cfg = c;
    }
}

// ---------------------------------------------------------------------------
// P1: features int32 -> f32 matrix; per-row s_feat[v] = feat[v] . wf
// grid = VV blocks, 256 threads
// ---------------------------------------------------------------------------
__global__ void k_p1(const int* __restrict__ feat, const float* __restrict__ w) {
    int v = blockIdx.x, f = threadIdx.x;
    float x = (float)feat[(size_t)v * FF + f];
    g_Bf[(size_t)v * FF + f] = x;
    float p = x * w[1 + f];
    #pragma unroll
    for (int o = 16; o; o >>= 1) p += __shfl_down_sync(0xffffffffu, p, o);
    __shared__ float sred[8];
    if ((f & 31) == 0) sred[f >> 5] = p;
    __syncthreads();
    if (f == 0) {
        float s = 0.f;
        #pragma unroll
        for (int i = 0; i < 8; i++) s += sred[i];
        g_sfeat[v] = s;
    }
}

// ---------------------------------------------------------------------------
// P2: A rows = wf * feat[u]; row bias; targets. grid = RPAD blocks, 256 thr
// ---------------------------------------------------------------------------
__global__ void k_p2(const int* __restrict__ seq32,
                     const int* __restrict__ feat,
                     const float* __restrict__ w) {
    int r = blockIdx.x, f = threadIdx.x;
    if (r < RR) {
        int b = r / (LLEN - 1), t = r % (LLEN - 1);
        int st = g_cfg.sstride;
        int u = seq32[(b * LLEN + t) * st] & VMASK;        // crash-proof gather
        g_A[(size_t)r * FF + f] = w[1 + f] * (float)feat[(size_t)u * FF + f];
        if (f == 0) {
            g_rowbias[r] = g_cfg.w0 * (g_cfg.W - g_sfeat[u]);
            g_tgt[r] = seq32[(b * LLEN + t + 1) * st] & VMASK;
        }
    } else {
        g_A[(size_t)r * FF + f] = 0.f;
        if (f == 0) { g_rowbias[r] = 0.f; g_tgt[r] = 0; }
    }
}

// ---------------------------------------------------------------------------
// Main fused GEMM + partial logsumexp.
// Block tile 128x128, thread tile 8x8, K chunked by 32 through smem.
// grid = (NT, MT), 256 threads.
// ---------------------------------------------------------------------------
__global__ __launch_bounds__(256, 2) void k_gemm() {
    __shared__ float As[KC][BM];       // [k][m] transposed
    __shared__ float Bs[KC][BN];       // [k][n] transposed
    __shared__ float red_m[BM][16];
    __shared__ float red_s[BM][16];

    const int tid = threadIdx.x;
    const int tx = tid & 15, ty = tid >> 4;
    const int m0 = blockIdx.y * BM, n0 = blockIdx.x * BN;
    const int ldrow = tid >> 3;          // 0..31
    const int ldc   = (tid & 7) << 2;    // 0,4,...,28

    float acc[8][8];
    #pragma unroll
    for (int i = 0; i < 8; i++)
        #pragma unroll
        for (int j = 0; j < 8; j++) acc[i][j] = 0.f;

    for (int k0 = 0; k0 < FF; k0 += KC) {
        #pragma unroll
        for (int p = 0; p < 4; p++) {
            int row = ldrow + p * 32;
            float4 a = *(const float4*)&g_A[(size_t)(m0 + row) * FF + k0 + ldc];
            As[ldc + 0][row] = a.x; As[ldc + 1][row] = a.y;
            As[ldc + 2][row] = a.z; As[ldc + 3][row] = a.w;
            float4 b = *(const float4*)&g_Bf[(size_t)(n0 + row) * FF + k0 + ldc];
            Bs[ldc + 0][row] = b.x; Bs[ldc + 1][row] = b.y;
            Bs[ldc + 2][row] = b.z; Bs[ldc + 3][row] = b.w;
        }
        __syncthreads();
        #pragma unroll
        for (int k = 0; k < KC; k++) {
            float4 a0 = *(const float4*)&As[k][ty * 8];
            float4 a1 = *(const float4*)&As[k][ty * 8 + 4];
            float4 b0 = *(const float4*)&Bs[k][tx * 8];
            float4 b1 = *(const float4*)&Bs[k][tx * 8 + 4];
            float av[8] = {a0.x, a0.y, a0.z, a0.w, a1.x, a1.y, a1.z, a1.w};
            float bv[8] = {b0.x, b0.y, b0.z, b0.w, b1.x, b1.y, b1.z, b1.w};
            #pragma unroll
            for (int i = 0; i < 8; i++)
                #pragma unroll
                for (int j = 0; j < 8; j++)
                    acc[i][j] = fmaf(av[i], bv[j], acc[i][j]);
        }
        __syncthreads();
    }

    // Epilogue: logits + thresholded online logsumexp over this v-tile
    Cfg c = g_cfg;
    float sv[8];
    #pragma unroll
    for (int j = 0; j < 8; j++) sv[j] = g_sfeat[n0 + tx * 8 + j];

    #pragma unroll
    for (int i = 0; i < 8; i++) {
        int m = ty * 8 + i;
        float rb = g_rowbias[m0 + m];
        float mi = neg_inf(), si = 0.f;
        #pragma unroll
        for (int j = 0; j < 8; j++) {
            float x = c.w0x2 * acc[i][j] - c.w0 * sv[j] + rb;
            if (!c.flag || x > c.thresh) {   // when flag: max logit = w0*W, skip negligible terms
                if (x > mi) { si = si * __expf(mi - x) + 1.0f; mi = x; }
                else        { si += __expf(x - mi); }
            }
        }
        red_m[m][tx] = mi;
        red_s[m][tx] = si;
    }
    __syncthreads();

    if (tid < BM) {
        float mm = neg_inf(), ss = 0.f;
        #pragma unroll
        for (int k = 0; k < 16; k++) {
            float mk = red_m[tid][k], sk = red_s[tid][k];
            if (sk > 0.f) {
                if (mk > mm) { ss = ss * __expf(mm - mk) + sk; mm = mk; }
                else         { ss += sk * __expf(mk - mm); }
            }
        }
        g_pm[(size_t)(m0 + tid) * NT + blockIdx.x] = mm;
        g_ps[(size_t)(m0 + tid) * NT + blockIdx.x] = ss;
    }
}

// ---------------------------------------------------------------------------
// Final: combine per-row partials, recompute target logit, reduce to scalar.
// Single block, 1024 threads = 32 warps; warp w handles rows w, w+32, ...
// ---------------------------------------------------------------------------
__global__ void k_final(float* __restrict__ out) {
    __shared__ float warp_sum[32];
    int tid = threadIdx.x, lane = tid & 31, wid = tid >> 5;
    float local = 0.f;

    for (int r = wid; r < RR; r += 32) {
        // combine NT=64 partials: lane reads 2
        float mm = neg_inf(), ss = 0.f;
        #pragma unroll
        for (int q = 0; q < 2; q++) {
            int k = lane + 32 * q;
            float mk = g_pm[(size_t)r * NT + k], sk = g_ps[(size_t)r * NT + k];
            if (sk > 0.f) {
                if (mk > mm) { ss = ss * __expf(mm - mk) + sk; mm = mk; }
                else         { ss += sk * __expf(mk - mm); }
            }
        }
        #pragma unroll
        for (int o = 16; o; o >>= 1) {
            float mo = __shfl_down_sync(0xffffffffu, mm, o);
            float so = __shfl_down_sync(0xffffffffu, ss, o);
            if (so > 0.f) {
                if (mo > mm) { ss = ss * __expf(mm - mo) + so; mm = mo; }
                else         { ss += so * __expf(mo - mm); }
            }
        }
        // target logit: dot(A_row, feat[tgt]) with coalesced float4 loads
        int tg = g_tgt[r];
        float dot = 0.f;
        #pragma unroll
        for (int q = 0; q < 2; q++) {
            float4 a = *(const float4*)&g_A[(size_t)r * FF + q * 128 + lane * 4];
            float4 b = *(const float4*)&g_Bf[(size_t)tg * FF + q * 128 + lane * 4];
            dot += a.x * b.x + a.y * b.y + a.z * b.z + a.w * b.w;
        }
        #pragma unroll
        for (int o = 16; o; o >>= 1) dot += __shfl_down_sync(0xffffffffu, dot, o);

        if (lane == 0) {
            float lse = mm + logf(ss);
            float xt  = g_cfg.w0x2 * dot - g_cfg.w0 * g_sfeat[tg] + g_rowbias[r];
            local += lse - xt;
        }
    }
    if (lane == 0) warp_sum[wid] = local;
    __syncthreads();
    if (tid == 0) {
        float tot = 0.f;
        #pragma unroll
        for (int i = 0; i < 32; i++) tot += warp_sum[i];
        out[0] = tot + (float)BBATCH * logf((float)VV);
    }
}

// ---------------------------------------------------------------------------
extern "C" void kernel_launch(void* const* d_in, const int* in_sizes, int n_in,
                              void* d_out, int out_size) {
    // Identify inputs by element count (order-agnostic):
    //   weights  : 257 floats
    //   features : 8192*256 = 2097152 int32
    //   sequences: 32*64   = 2048 (int32 OR int64 — detected on device)
    const float* w    = 0;
    const int*   feat = 0;
    const int*   seq  = 0;
    for (int i = 0; i < n_in; i++) {
        if      (in_sizes[i] == FF + 1)        w    = (const float*)d_in[i];
        else if (in_sizes[i] == VV * FF)       feat = (const int*)d_in[i];
        else if (in_sizes[i] == BBATCH * LLEN) seq  = (const int*)d_in[i];
    }
    if (!w || !feat || !seq) {
        w    = (const float*)d_in[0];
        feat = (const int*)d_in[1];
        seq  = (const int*)d_in[2];
    }

    k_p0<<<1, 256>>>(w, seq);
    k_p1<<<VV, 256>>>(feat, w);
    k_p2<<<RPAD, 256>>>(seq, feat, w);
    k_gemm<<<dim3(NT, MT), 256>>>();
    k_final<<<1, 1024>>>((float*)d_out);
}

// round 5
// speedup vs baseline: 5.9129x; 5.9129x over previous
#include <cuda_runtime.h>
#include <math.h>
#include <stdint.h>

// Problem constants (V=8192, F=256, B=32, L=64)
#define VV     8192
#define FF     256
#define BBATCH 32
#define LLEN   64
#define RR     2016
#define RPAD   2048
#define BM     128
#define BN     128
#define KC     32
#define NW     8           // 256 bits = 8 x u32 words
#define NT     64          // 8192/128 n-tiles
#define MT     16          // 2048/128 m-tiles
#define VMASK  (VV - 1)

struct Cfg { float w0, W, w0x2, thresh, wfc; int flag; int sstride; };

__device__ Cfg      g_cfg;
__device__ int      g_use_pc;                 // popcount fast path valid
__device__ float    g_Bf[VV * FF];            // features f32 (fallback + final dot)
__device__ float    g_A[RPAD * FF];           // wf*feat[u] f32
__device__ uint32_t g_Bbits[VV * NW];         // packed features (256 KB)
__device__ uint32_t g_Abits[RPAD * NW];       // packed prev-token features
__device__ float    g_sfeat[VV];
__device__ float    g_rowbias[RPAD];
__device__ int      g_tgt[RPAD];
__device__ float    g_pm[RPAD * NT];
__device__ float    g_ps[RPAD * NT];
__device__ float    g_rownll[RPAD];

__device__ __forceinline__ float neg_inf() { return __int_as_float(0xff800000u); }

// ---------------------------------------------------------------------------
// P0: scalars — W, flag, threshold, wf-uniformity, seq dtype sniff
// ---------------------------------------------------------------------------
__global__ void k_p0(const float* __restrict__ w, const int* __restrict__ seq32) {
    int tid = threadIdx.x;                    // 256 threads, f = tid
    float wf = w[1 + tid];
    float s = wf, mn = wf, mx = wf;
    #pragma unroll
    for (int o = 16; o; o >>= 1) {
        s  += __shfl_down_sync(0xffffffffu, s, o);
        mn  = fminf(mn, __shfl_down_sync(0xffffffffu, mn, o));
        mx  = fmaxf(mx, __shfl_down_sync(0xffffffffu, mx, o));
    }
    __shared__ float ssum[8], smin[8], smax[8];
    if ((tid & 31) == 0) { ssum[tid >> 5] = s; smin[tid >> 5] = mn; smax[tid >> 5] = mx; }
    __syncthreads();
    if (tid == 0) {
        float S = 0.f, MN = 3.0e38f, MX = -3.0e38f;
        #pragma unroll
        for (int i = 0; i < 8; i++) { S += ssum[i]; MN = fminf(MN, smin[i]); MX = fmaxf(MX, smax[i]); }
        float w0 = w[0];
        Cfg c;
        c.w0 = w0; c.W = S; c.w0x2 = 2.0f * w0;
        c.flag = (w0 >= 0.f && MN >= 0.f) ? 1 : 0;   // max logit provably = w0*W (at v=u)
        c.thresh = w0 * S - 33.0f;
        c.wfc = MN;                                   // uniform weight value (if uniform)
        int is64 = 1;
        for (int i = 0; i < 32; i++)
            if (seq32[2 * i + 1] != 0) { is64 = 0; break; }
        c.sstride = is64 ? 2 : 1;
        g_cfg = c;
        g_use_pc = (MN == MX) ? 1 : 0;   // binarity of features ANDed in k_p1
    }
}

// ---------------------------------------------------------------------------
// P1: features -> f32; bit-pack via ballot; s_feat; binarity check
// ---------------------------------------------------------------------------
__global__ void k_p1(const int* __restrict__ feat, const float* __restrict__ w) {
    int v = blockIdx.x, f = threadIdx.x;
    float x = (float)feat[(size_t)v * FF + f];
    g_Bf[(size_t)v * FF + f] = x;
    // packed bits: warp w -> word w
    uint32_t word = __ballot_sync(0xffffffffu, x != 0.f);
    if ((f & 31) == 0) g_Bbits[v * NW + (f >> 5)] = word;
    int ok = (x == 0.f || x == 1.f);
    if (!__syncthreads_and(ok)) {
        if (f == 0) atomicAnd(&g_use_pc, 0);
    }
    float p = x * w[1 + f];
    #pragma unroll
    for (int o = 16; o; o >>= 1) p += __shfl_down_sync(0xffffffffu, p, o);
    __shared__ float sred[8];
    if ((f & 31) == 0) sred[f >> 5] = p;
    __syncthreads();
    if (f == 0) {
        float s2 = 0.f;
        #pragma unroll
        for (int i = 0; i < 8; i++) s2 += sred[i];
        g_sfeat[v] = s2;
    }
}

// ---------------------------------------------------------------------------
// P2: A rows f32 + packed bits; row bias; targets
// ---------------------------------------------------------------------------
__global__ void k_p2(const int* __restrict__ seq32,
                     const int* __restrict__ feat,
                     const float* __restrict__ w) {
    int r = blockIdx.x, f = threadIdx.x;
    if (r < RR) {
        int b = r / (LLEN - 1), t = r % (LLEN - 1);
        int st = g_cfg.sstride;
        int u = seq32[(b * LLEN + t) * st] & VMASK;
        int fv = feat[(size_t)u * FF + f];
        g_A[(size_t)r * FF + f] = w[1 + f] * (float)fv;
        uint32_t word = __ballot_sync(0xffffffffu, fv != 0);
        if ((f & 31) == 0) g_Abits[r * NW + (f >> 5)] = word;
        if (f == 0) {
            g_rowbias[r] = g_cfg.w0 * (g_cfg.W - g_sfeat[u]);
            g_tgt[r] = seq32[(b * LLEN + t + 1) * st] & VMASK;
        }
    } else {
        g_A[(size_t)r * FF + f] = 0.f;
        uint32_t word = __ballot_sync(0xffffffffu, 0);
        if ((f & 31) == 0) g_Abits[r * NW + (f >> 5)] = word;
        if (f == 0) { g_rowbias[r] = 0.f; g_tgt[r] = 0; }
    }
}

// ---------------------------------------------------------------------------
// Popcount GEMM + fused thresholded logsumexp. grid (NT, MT), 256 threads.
// dot(u,v) = wfc * popc(bits_u & bits_v); 8x8 outputs per thread.
// ---------------------------------------------------------------------------
__global__ __launch_bounds__(256, 2) void k_pc() {
    if (!g_use_pc) return;
    __shared__ uint32_t sA[BM][NW];    // word index XOR-swizzled by (row>>3)&7
    __shared__ uint32_t sB[BN][NW];
    __shared__ float    svf[BN];
    __shared__ float    red_m[BM][16];
    __shared__ float    red_s[BM][16];

    const int tid = threadIdx.x;
    const int tx = tid & 15, ty = tid >> 4;
    const int m0 = blockIdx.y * BM, n0 = blockIdx.x * BN;

    // load: each thread one uint4 of A and one of B (row = tid>>1, half = tid&1)
    {
        int r = tid >> 1, h = (tid & 1) << 2;
        int swa = (r >> 3) & 7;
        uint4 a = *(const uint4*)&g_Abits[(size_t)(m0 + r) * NW + h];
        sA[r][(h + 0) ^ swa] = a.x; sA[r][(h + 1) ^ swa] = a.y;
        sA[r][(h + 2) ^ swa] = a.z; sA[r][(h + 3) ^ swa] = a.w;
        uint4 b = *(const uint4*)&g_Bbits[(size_t)(n0 + r) * NW + h];
        sB[r][(h + 0) ^ swa] = b.x; sB[r][(h + 1) ^ swa] = b.y;
        sB[r][(h + 2) ^ swa] = b.z; sB[r][(h + 3) ^ swa] = b.w;
    }
    if (tid < BN) svf[tid] = g_cfg.w0 * g_sfeat[n0 + tid];
    __syncthreads();

    int acc[8][8];
    #pragma unroll
    for (int i = 0; i < 8; i++)
        #pragma unroll
        for (int j = 0; j < 8; j++) acc[i][j] = 0;

    const int swy = ty & 7, swx = tx & 7;
    #pragma unroll
    for (int w = 0; w < NW; w++) {
        uint32_t av[8], bv[8];
        #pragma unroll
        for (int i = 0; i < 8; i++) av[i] = sA[ty * 8 + i][w ^ swy];
        #pragma unroll
        for (int j = 0; j < 8; j++) bv[j] = sB[tx * 8 + j][w ^ swx];
        #pragma unroll
        for (int i = 0; i < 8; i++)
            #pragma unroll
            for (int j = 0; j < 8; j++)
                acc[i][j] += __popc(av[i] & bv[j]);
    }

    // Epilogue: x = 2*w0*wfc*cnt - w0*s_v + rb, thresholded online LSE
    const Cfg c = g_cfg;
    const float cw = c.w0x2 * c.wfc;
    float sv[8];
    #pragma unroll
    for (int j = 0; j < 8; j++) sv[j] = svf[tx * 8 + j];

    #pragma unroll
    for (int i = 0; i < 8; i++) {
        int m = ty * 8 + i;
        float rb = g_rowbias[m0 + m];
        float mi = neg_inf(), si = 0.f;
        #pragma unroll
        for (int j = 0; j < 8; j++) {
            float x = fmaf(cw, (float)acc[i][j], rb - sv[j]);
            if (!c.flag || x > c.thresh) {
                if (x > mi) { si = si * __expf(mi - x) + 1.0f; mi = x; }
                else        { si += __expf(x - mi); }
            }
        }
        red_m[m][tx] = mi;
        red_s[m][tx] = si;
    }
    __syncthreads();

    if (tid < BM) {
        float mm = neg_inf(), ss = 0.f;
        #pragma unroll
        for (int k = 0; k < 16; k++) {
            float mk = red_m[tid][k], sk = red_s[tid][k];
            if (sk > 0.f) {
                if (mk > mm) { ss = ss * __expf(mm - mk) + sk; mm = mk; }
                else         { ss += sk * __expf(mk - mm); }
            }
        }
        g_pm[(size_t)(m0 + tid) * NT + blockIdx.x] = mm;
        g_ps[(size_t)(m0 + tid) * NT + blockIdx.x] = ss;
    }
}

// ---------------------------------------------------------------------------
// fp32 SIMT fallback GEMM (runs only if !g_use_pc)
// ---------------------------------------------------------------------------
__global__ __launch_bounds__(256, 2) void k_gemm() {
    if (g_use_pc) return;
    __shared__ float As[KC][BM];
    __shared__ float Bs[KC][BN];
    __shared__ float red_m[BM][16];
    __shared__ float red_s[BM][16];

    const int tid = threadIdx.x;
    const int tx = tid & 15, ty = tid >> 4;
    const int m0 = blockIdx.y * BM, n0 = blockIdx.x * BN;
    const int ldrow = tid >> 3;
    const int ldc   = (tid & 7) << 2;

    float acc[8][8];
    #pragma unroll
    for (int i = 0; i < 8; i++)
        #pragma unroll
        for (int j = 0; j < 8; j++) acc[i][j] = 0.f;

    for (int k0 = 0; k0 < FF; k0 += KC) {
        #pragma unroll
        for (int q = 0; q < 4; q++) {
            int row = ldrow + q * 32;
            float4 a = *(const float4*)&g_A[(size_t)(m0 + row) * FF + k0 + ldc];
            As[ldc + 0][row] = a.x; As[ldc + 1][row] = a.y;
            As[ldc + 2][row] = a.z; As[ldc + 3][row] = a.w;
            float4 b = *(const float4*)&g_Bf[(size_t)(n0 + row) * FF + k0 + ldc];
            Bs[ldc + 0][row] = b.x; Bs[ldc + 1][row] = b.y;
            Bs[ldc + 2][row] = b.z; Bs[ldc + 3][row] = b.w;
        }
        __syncthreads();
        #pragma unroll
        for (int k = 0; k < KC; k++) {
            float4 a0 = *(const float4*)&As[k][ty * 8];
            float4 a1 = *(const float4*)&As[k][ty * 8 + 4];
            float4 b0 = *(const float4*)&Bs[k][tx * 8];
            float4 b1 = *(const float4*)&Bs[k][tx * 8 + 4];
            float av[8] = {a0.x, a0.y, a0.z, a0.w, a1.x, a1.y, a1.z, a1.w};
            float bv[8] = {b0.x, b0.y, b0.z, b0.w, b1.x, b1.y, b1.z, b1.w};
            #pragma unroll
            for (int i = 0; i < 8; i++)
                #pragma unroll
                for (int j = 0; j < 8; j++)
                    acc[i][j] = fmaf(av[i], bv[j], acc[i][j]);
        }
        __syncthreads();
    }

    Cfg c = g_cfg;
    float sv[8];
    #pragma unroll
    for (int j = 0; j < 8; j++) sv[j] = g_sfeat[n0 + tx * 8 + j];

    #pragma unroll
    for (int i = 0; i < 8; i++) {
        int m = ty * 8 + i;
        float rb = g_rowbias[m0 + m];
        float mi = neg_inf(), si = 0.f;
        #pragma unroll
        for (int j = 0; j < 8; j++) {
            float x = c.w0x2 * acc[i][j] - c.w0 * sv[j] + rb;
            if (!c.flag || x > c.thresh) {
                if (x > mi) { si = si * __expf(mi - x) + 1.0f; mi = x; }
                else        { si += __expf(x - mi); }
            }
        }
        red_m[m][tx] = mi;
        red_s[m][tx] = si;
    }
    __syncthreads();

    if (tid < BM) {
        float mm = neg_inf(), ss = 0.f;
        #pragma unroll
        for (int k = 0; k < 16; k++) {
            float mk = red_m[tid][k], sk = red_s[tid][k];
            if (sk > 0.f) {
                if (mk > mm) { ss = ss * __expf(mm - mk) + sk; mm = mk; }
                else         { ss += sk * __expf(mk - mm); }
            }
        }
        g_pm[(size_t)(m0 + tid) * NT + blockIdx.x] = mm;
        g_ps[(size_t)(m0 + tid) * NT + blockIdx.x] = ss;
    }
}

// ---------------------------------------------------------------------------
// Final stage 1: one warp per row -> per-row NLL. grid 63 x 1024 threads.
// ---------------------------------------------------------------------------
__global__ void k_final1() {
    int tid = threadIdx.x, lane = tid & 31, wid = tid >> 5;
    int r = blockIdx.x * 32 + wid;
    if (r >= RR) return;

    float mm = neg_inf(), ss = 0.f;
    #pragma unroll
    for (int q = 0; q < 2; q++) {
        int k = lane + 32 * q;
        float mk = g_pm[(size_t)r * NT + k], sk = g_ps[(size_t)r * NT + k];
        if (sk > 0.f) {
            if (mk > mm) { ss = ss * __expf(mm - mk) + sk; mm = mk; }
            else         { ss += sk * __expf(mk - mm); }
        }
    }
    #pragma unroll
    for (int o = 16; o; o >>= 1) {
        float mo = __shfl_down_sync(0xffffffffu, mm, o);
        float so = __shfl_down_sync(0xffffffffu, ss, o);
        if (so > 0.f) {
            if (mo > mm) { ss = ss * __expf(mm - mo) + so; mm = mo; }
            else         { ss += so * __expf(mo - mm); }
        }
    }
    int tg = g_tgt[r];
    float dot = 0.f;
    #pragma unroll
    for (int q = 0; q < 2; q++) {
        float4 a = *(const float4*)&g_A[(size_t)r * FF + q * 128 + lane * 4];
        float4 b = *(const float4*)&g_Bf[(size_t)tg * FF + q * 128 + lane * 4];
        dot += a.x * b.x + a.y * b.y + a.z * b.z + a.w * b.w;
    }
    #pragma unroll
    for (int o = 16; o; o >>= 1) dot += __shfl_down_sync(0xffffffffu, dot, o);

    if (lane == 0) {
        float lse = mm + logf(ss);
        float xt  = g_cfg.w0x2 * dot - g_cfg.w0 * g_sfeat[tg] + g_rowbias[r];
        g_rownll[r] = lse - xt;
    }
}

// ---------------------------------------------------------------------------
// Final stage 2: deterministic tree-sum of row NLLs.
// ---------------------------------------------------------------------------
__global__ void k_final2(float* __restrict__ out) {
    __shared__ float red[1024];
    int tid = threadIdx.x;
    float v = 0.f;
    if (tid < RR)        v += g_rownll[tid];
    if (tid + 1024 < RR) v += g_rownll[tid + 1024];
    red[tid] = v;
    __syncthreads();
    #pragma unroll
    for (int s = 512; s > 0; s >>= 1) {
        if (tid < s) red[tid] += red[tid + s];
        __syncthreads();
    }
    if (tid == 0) out[0] = red[0] + (float)BBATCH * logf((float)VV);
}

// ---------------------------------------------------------------------------
extern "C" void kernel_launch(void* const* d_in, const int* in_sizes, int n_in,
                              void* d_out, int out_size) {
    const float* w    = 0;
    const int*   feat = 0;
    const int*   seq  = 0;
    for (int i = 0; i < n_in; i++) {
        if      (in_sizes[i] == FF + 1)        w    = (const float*)d_in[i];
        else if (in_sizes[i] == VV * FF)       feat = (const int*)d_in[i];
        else if (in_sizes[i] == BBATCH * LLEN) seq  = (const int*)d_in[i];
    }
    if (!w || !feat || !seq) {
        w    = (const float*)d_in[0];
        feat = (const int*)d_in[1];
        seq  = (const int*)d_in[2];
    }

    k_p0<<<1, 256>>>(w, seq);
    k_p1<<<VV, 256>>>(feat, w);
    k_p2<<<RPAD, 256>>>(seq, feat, w);
    k_pc<<<dim3(NT, MT), 256>>>();
    k_gemm<<<dim3(NT, MT), 256>>>();
    k_final1<<<63, 1024>>>();
    k_final2<<<1, 1024>>>((float*)d_out);
}

// round 6
// speedup vs baseline: 6.1223x; 1.0354x over previous
#include <cuda_runtime.h>
#include <math.h>
#include <stdint.h>

// Problem constants (V=8192, F=256, B=32, L=64)
#define VV     8192
#define FF     256
#define BBATCH 32
#define LLEN   64
#define RR     2016
#define RPAD   2048
#define BM     128
#define BN     128
#define KC     32
#define NW     8           // 256 bits = 8 x u32 words
#define NT     64          // fallback n-tiles (BN=128)
#define PCN    64          // popcount path: n-cols per CTA
#define PCNT   128         // popcount path: n-tiles
#define NTMAX  128         // pm/ps stride
#define MT     16          // 2048/128 m-tiles
#define VMASK  (VV - 1)

struct Cfg { float w0, W, w0x2, thresh, wfc; int flag; int sstride; };

__device__ Cfg      g_cfg;
__device__ int      g_use_pc;
__device__ float    g_Bf[VV * FF];            // features f32 (fallback + final dot)
__device__ float    g_A[RPAD * FF];           // wf*feat[u] f32
__device__ uint32_t g_Bbits[VV * NW];
__device__ uint32_t g_Abits[RPAD * NW];
__device__ float    g_sfeat[VV];
__device__ float    g_rowbias[RPAD];
__device__ int      g_tgt[RPAD];
__device__ float    g_pm[RPAD * NTMAX];
__device__ float    g_ps[RPAD * NTMAX];
__device__ float    g_rownll[RPAD];

__device__ __forceinline__ float neg_inf() { return __int_as_float(0xff800000u); }

// ---------------------------------------------------------------------------
// P0: scalars — W, flag, threshold, wf-uniformity, seq dtype sniff
// ---------------------------------------------------------------------------
__global__ void k_p0(const float* __restrict__ w, const int* __restrict__ seq32) {
    int tid = threadIdx.x;
    float wf = w[1 + tid];
    float s = wf, mn = wf, mx = wf;
    #pragma unroll
    for (int o = 16; o; o >>= 1) {
        s  += __shfl_down_sync(0xffffffffu, s, o);
        mn  = fminf(mn, __shfl_down_sync(0xffffffffu, mn, o));
        mx  = fmaxf(mx, __shfl_down_sync(0xffffffffu, mx, o));
    }
    __shared__ float ssum[8], smin[8], smax[8];
    if ((tid & 31) == 0) { ssum[tid >> 5] = s; smin[tid >> 5] = mn; smax[tid >> 5] = mx; }
    __syncthreads();
    if (tid == 0) {
        float S = 0.f, MN = 3.0e38f, MX = -3.0e38f;
        #pragma unroll
        for (int i = 0; i < 8; i++) { S += ssum[i]; MN = fminf(MN, smin[i]); MX = fmaxf(MX, smax[i]); }
        float w0 = w[0];
        Cfg c;
        c.w0 = w0; c.W = S; c.w0x2 = 2.0f * w0;
        c.flag = (w0 >= 0.f && MN >= 0.f) ? 1 : 0;
        c.thresh = w0 * S - 33.0f;
        c.wfc = MN;
        int is64 = 1;
        for (int i = 0; i < 32; i++)
            if (seq32[2 * i + 1] != 0) { is64 = 0; break; }
        c.sstride = is64 ? 2 : 1;
        g_cfg = c;
        g_use_pc = (MN == MX) ? 1 : 0;   // binarity ANDed in k_p1
    }
}

// ---------------------------------------------------------------------------
// P1: features -> f32; bit-pack via ballot; s_feat; binarity check
// ---------------------------------------------------------------------------
__global__ void k_p1(const int* __restrict__ feat, const float* __restrict__ w) {
    int v = blockIdx.x, f = threadIdx.x;
    float x = (float)feat[(size_t)v * FF + f];
    g_Bf[(size_t)v * FF + f] = x;
    uint32_t word = __ballot_sync(0xffffffffu, x != 0.f);
    if ((f & 31) == 0) g_Bbits[v * NW + (f >> 5)] = word;
    int ok = (x == 0.f || x == 1.f);
    if (!__syncthreads_and(ok)) {
        if (f == 0) atomicAnd(&g_use_pc, 0);
    }
    float p = x * w[1 + f];
    #pragma unroll
    for (int o = 16; o; o >>= 1) p += __shfl_down_sync(0xffffffffu, p, o);
    __shared__ float sred[8];
    if ((f & 31) == 0) sred[f >> 5] = p;
    __syncthreads();
    if (f == 0) {
        float s2 = 0.f;
        #pragma unroll
        for (int i = 0; i < 8; i++) s2 += sred[i];
        g_sfeat[v] = s2;
    }
}

// ---------------------------------------------------------------------------
// P2: A rows f32 + packed bits; row bias; targets
// ---------------------------------------------------------------------------
__global__ void k_p2(const int* __restrict__ seq32,
                     const int* __restrict__ feat,
                     const float* __restrict__ w) {
    int r = blockIdx.x, f = threadIdx.x;
    if (r < RR) {
        int b = r / (LLEN - 1), t = r % (LLEN - 1);
        int st = g_cfg.sstride;
        int u = seq32[(b * LLEN + t) * st] & VMASK;
        int fv = feat[(size_t)u * FF + f];
        g_A[(size_t)r * FF + f] = w[1 + f] * (float)fv;
        uint32_t word = __ballot_sync(0xffffffffu, fv != 0);
        if ((f & 31) == 0) g_Abits[r * NW + (f >> 5)] = word;
        if (f == 0) {
            g_rowbias[r] = g_cfg.w0 * (g_cfg.W - g_sfeat[u]);
            g_tgt[r] = seq32[(b * LLEN + t + 1) * st] & VMASK;
        }
    } else {
        g_A[(size_t)r * FF + f] = 0.f;
        uint32_t word = __ballot_sync(0xffffffffu, 0);
        if ((f & 31) == 0) g_Abits[r * NW + (f >> 5)] = word;
        if (f == 0) { g_rowbias[r] = 0.f; g_tgt[r] = 0; }
    }
}

// ---------------------------------------------------------------------------
// Popcount (hamming) GEMM + exp-table epilogue.
// Tile 128(m) x 64(n) per CTA, 256 threads, 4x8 outputs/thread.
// logit = delta*(F - ham); contribution = table[ham] = exp(-delta*(ham-h*)).
// grid (PCNT, MT).
// ---------------------------------------------------------------------------
__global__ __launch_bounds__(256, 4) void k_pc() {
    if (!g_use_pc) return;
    __shared__ uint32_t sA[BM][NW];    // word idx ^ (ty&7)
    __shared__ uint32_t sB[PCN][NW];   // word idx ^ tx
    __shared__ float    tbl[257];
    __shared__ float    red[BM][8];

    const int tid = threadIdx.x;
    const int tx = tid & 7, ty = tid >> 3;         // tx: 8 col-groups, ty: 32 row-groups
    const int n0 = blockIdx.x * PCN, m0 = blockIdx.y * BM;
    const Cfg c = g_cfg;
    const float delta = c.w0 * c.wfc;
    const float hstar = (delta >= 0.f) ? 0.f : 256.f;

    tbl[tid] = __expf(-delta * ((float)tid - hstar));
    if (tid == 0) tbl[256] = __expf(-delta * (256.f - hstar));

    // stage A bits: 128 rows x 8 words; thread t: row=t>>1, half=(t&1)*4
    {
        int r = tid >> 1, h = (tid & 1) << 2;
        int sw = (r >> 2) & 7;                      // equals ty&7 of the consumer
        uint4 a = *(const uint4*)&g_Abits[(size_t)(m0 + r) * NW + h];
        sA[r][(h + 0) ^ sw] = a.x; sA[r][(h + 1) ^ sw] = a.y;
        sA[r][(h + 2) ^ sw] = a.z; sA[r][(h + 3) ^ sw] = a.w;
    }
    // stage B bits: 64 rows x 8 words; threads 0..127
    if (tid < 128) {
        int r = tid >> 1, h = (tid & 1) << 2;
        int sw = (r >> 3) & 7;                      // equals tx of the consumer
        uint4 b = *(const uint4*)&g_Bbits[(size_t)(n0 + r) * NW + h];
        sB[r][(h + 0) ^ sw] = b.x; sB[r][(h + 1) ^ sw] = b.y;
        sB[r][(h + 2) ^ sw] = b.z; sB[r][(h + 3) ^ sw] = b.w;
    }
    __syncthreads();

    int acc[4][8];
    #pragma unroll
    for (int i = 0; i < 4; i++)
        #pragma unroll
        for (int j = 0; j < 8; j++) acc[i][j] = 0;

    const int swa = ty & 7;
    #pragma unroll
    for (int w = 0; w < NW; w++) {
        uint32_t av[4], bv[8];
        #pragma unroll
        for (int i = 0; i < 4; i++) av[i] = sA[ty * 4 + i][w ^ swa];
        #pragma unroll
        for (int j = 0; j < 8; j++) bv[j] = sB[tx * 8 + j][w ^ tx];
        #pragma unroll
        for (int i = 0; i < 4; i++)
            #pragma unroll
            for (int j = 0; j < 8; j++)
                acc[i][j] += __popc(av[i] ^ bv[j]);   // hamming distance accumulation
    }

    // per-thread partial sums via table gather
    #pragma unroll
    for (int i = 0; i < 4; i++) {
        float s = 0.f;
        #pragma unroll
        for (int j = 0; j < 8; j++) s += tbl[acc[i][j]];
        red[ty * 4 + i][tx] = s;
    }
    __syncthreads();

    if (tid < BM) {
        float s = 0.f;
        #pragma unroll
        for (int k = 0; k < 8; k++) s += red[tid][k];
        g_pm[(size_t)(m0 + tid) * NTMAX + blockIdx.x] = delta * (256.f - hstar); // max logit scale
        g_ps[(size_t)(m0 + tid) * NTMAX + blockIdx.x] = s;
    }
}

// ---------------------------------------------------------------------------
// fp32 SIMT fallback GEMM (runs only if !g_use_pc). grid (NT, MT).
// ---------------------------------------------------------------------------
__global__ __launch_bounds__(256, 2) void k_gemm() {
    if (g_use_pc) return;
    __shared__ float As[KC][BM];
    __shared__ float Bs[KC][BN];
    __shared__ float red_m[BM][16];
    __shared__ float red_s[BM][16];

    const int tid = threadIdx.x;
    const int tx = tid & 15, ty = tid >> 4;
    const int m0 = blockIdx.y * BM, n0 = blockIdx.x * BN;
    const int ldrow = tid >> 3;
    const int ldc   = (tid & 7) << 2;

    float acc[8][8];
    #pragma unroll
    for (int i = 0; i < 8; i++)
        #pragma unroll
        for (int j = 0; j < 8; j++) acc[i][j] = 0.f;

    for (int k0 = 0; k0 < FF; k0 += KC) {
        #pragma unroll
        for (int q = 0; q < 4; q++) {
            int row = ldrow + q * 32;
            float4 a = *(const float4*)&g_A[(size_t)(m0 + row) * FF + k0 + ldc];
            As[ldc + 0][row] = a.x; As[ldc + 1][row] = a.y;
            As[ldc + 2][row] = a.z; As[ldc + 3][row] = a.w;
            float4 b = *(const float4*)&g_Bf[(size_t)(n0 + row) * FF + k0 + ldc];
            Bs[ldc + 0][row] = b.x; Bs[ldc + 1][row] = b.y;
            Bs[ldc + 2][row] = b.z; Bs[ldc + 3][row] = b.w;
        }
        __syncthreads();
        #pragma unroll
        for (int k = 0; k < KC; k++) {
            float4 a0 = *(const float4*)&As[k][ty * 8];
            float4 a1 = *(const float4*)&As[k][ty * 8 + 4];
            float4 b0 = *(const float4*)&Bs[k][tx * 8];
            float4 b1 = *(const float4*)&Bs[k][tx * 8 + 4];
            float av[8] = {a0.x, a0.y, a0.z, a0.w, a1.x, a1.y, a1.z, a1.w};
            float bv[8] = {b0.x, b0.y, b0.z, b0.w, b1.x, b1.y, b1.z, b1.w};
            #pragma unroll
            for (int i = 0; i < 8; i++)
                #pragma unroll
                for (int j = 0; j < 8; j++)
                    acc[i][j] = fmaf(av[i], bv[j], acc[i][j]);
        }
        __syncthreads();
    }

    Cfg c = g_cfg;
    float sv[8];
    #pragma unroll
    for (int j = 0; j < 8; j++) sv[j] = g_sfeat[n0 + tx * 8 + j];

    #pragma unroll
    for (int i = 0; i < 8; i++) {
        int m = ty * 8 + i;
        float rb = g_rowbias[m0 + m];
        float mi = neg_inf(), si = 0.f;
        #pragma unroll
        for (int j = 0; j < 8; j++) {
            float x = c.w0x2 * acc[i][j] - c.w0 * sv[j] + rb;
            if (!c.flag || x > c.thresh) {
                if (x > mi) { si = si * __expf(mi - x) + 1.0f; mi = x; }
                else        { si += __expf(x - mi); }
            }
        }
        red_m[m][tx] = mi;
        red_s[m][tx] = si;
    }
    __syncthreads();

    if (tid < BM) {
        float mm = neg_inf(), ss = 0.f;
        #pragma unroll
        for (int k = 0; k < 16; k++) {
            float mk = red_m[tid][k], sk = red_s[tid][k];
            if (sk > 0.f) {
                if (mk > mm) { ss = ss * __expf(mm - mk) + sk; mm = mk; }
                else         { ss += sk * __expf(mk - mm); }
            }
        }
        g_pm[(size_t)(m0 + tid) * NTMAX + blockIdx.x] = mm;
        g_ps[(size_t)(m0 + tid) * NTMAX + blockIdx.x] = ss;
    }
}

// ---------------------------------------------------------------------------
// Final stage 1: one warp per row -> per-row NLL. grid 63 x 1024 threads.
// ---------------------------------------------------------------------------
__global__ void k_final1() {
    int tid = threadIdx.x, lane = tid & 31, wid = tid >> 5;
    int r = blockIdx.x * 32 + wid;
    if (r >= RR) return;

    int ntiles = g_use_pc ? PCNT : NT;
    float mm = neg_inf(), ss = 0.f;
    for (int k = lane; k < ntiles; k += 32) {
        float mk = g_pm[(size_t)r * NTMAX + k], sk = g_ps[(size_t)r * NTMAX + k];
        if (sk > 0.f) {
            if (mk > mm) { ss = ss * __expf(mm - mk) + sk; mm = mk; }
            else         { ss += sk * __expf(mk - mm); }
        }
    }
    #pragma unroll
    for (int o = 16; o; o >>= 1) {
        float mo = __shfl_down_sync(0xffffffffu, mm, o);
        float so = __shfl_down_sync(0xffffffffu, ss, o);
        if (so > 0.f) {
            if (mo > mm) { ss = ss * __expf(mm - mo) + so; mm = mo; }
            else         { ss += so * __expf(mo - mm); }
        }
    }
    int tg = g_tgt[r];
    float dot = 0.f;
    #pragma unroll
    for (int q = 0; q < 2; q++) {
        float4 a = *(const float4*)&g_A[(size_t)r * FF + q * 128 + lane * 4];
        float4 b = *(const float4*)&g_Bf[(size_t)tg * FF + q * 128 + lane * 4];
        dot += a.x * b.x + a.y * b.y + a.z * b.z + a.w * b.w;
    }
    #pragma unroll
    for (int o = 16; o; o >>= 1) dot += __shfl_down_sync(0xffffffffu, dot, o);

    if (lane == 0) {
        float lse = mm + logf(ss);
        float xt  = g_cfg.w0x2 * dot - g_cfg.w0 * g_sfeat[tg] + g_rowbias[r];
        g_rownll[r] = lse - xt;
    }
}

// ---------------------------------------------------------------------------
// Final stage 2: deterministic tree-sum of row NLLs.
// ---------------------------------------------------------------------------
__global__ void k_final2(float* __restrict__ out) {
    __shared__ float red[1024];
    int tid = threadIdx.x;
    float v = 0.f;
    if (tid < RR)        v += g_rownll[tid];
    if (tid + 1024 < RR) v += g_rownll[tid + 1024];
    red[tid] = v;
    __syncthreads();
    #pragma unroll
    for (int s = 512; s > 0; s >>= 1) {
        if (tid < s) red[tid] += red[tid + s];
        __syncthreads();
    }
    if (tid == 0) out[0] = red[0] + (float)BBATCH * logf((float)VV);
}

// ---------------------------------------------------------------------------
extern "C" void kernel_launch(void* const* d_in, const int* in_sizes, int n_in,
                              void* d_out, int out_size) {
    const float* w    = 0;
    const int*   feat = 0;
    const int*   seq  = 0;
    for (int i = 0; i < n_in; i++) {
        if      (in_sizes[i] == FF + 1)        w    = (const float*)d_in[i];
        else if (in_sizes[i] == VV * FF)       feat = (const int*)d_in[i];
        else if (in_sizes[i] == BBATCH * LLEN) seq  = (const int*)d_in[i];
    }
    if (!w || !feat || !seq) {
        w    = (const float*)d_in[0];
        feat = (const int*)d_in[1];
        seq  = (const int*)d_in[2];
    }

    k_p0<<<1, 256>>>(w, seq);
    k_p1<<<VV, 256>>>(feat, w);
    k_p2<<<RPAD, 256>>>(seq, feat, w);
    k_pc<<<dim3(PCNT, MT), 256>>>();
    k_gemm<<<dim3(NT, MT), 256>>>();
    k_final1<<<63, 1024>>>();
    k_final2<<<1, 1024>>>((float*)d_out);
}

// round 7
// speedup vs baseline: 8.5166x; 1.3911x over previous
#include <cuda_runtime.h>
#include <math.h>
#include <stdint.h>

// Problem constants (V=8192, F=256, B=32, L=64)
#define VV     8192
#define FF     256
#define BBATCH 32
#define LLEN   64
#define RR     2016
#define RPAD   2048
#define BM     128
#define BN     128
#define KC     32
#define NW     8           // 256 bits = 8 x u32 words
#define NT     64          // fallback n-tiles (BN=128)
#define PCN    64          // popcount path: n-cols per CTA
#define PCNT   128         // popcount path: n-tiles
#define NTMAX  128         // pm/ps stride
#define MT     16          // 2048/128 m-tiles
#define VMASK  (VV - 1)

struct Cfg { float w0, W, w0x2, thresh, wfc, delta; int flag, sstride, ihhi; };

__device__ Cfg      g_cfg;
__device__ int      g_use_pc;
__device__ uint32_t g_Bbits[VV * NW];
__device__ uint32_t g_Abits[RPAD * NW];
__device__ int      g_useq[RPAD];
__device__ float    g_sfeat[VV];
__device__ float    g_rowbias[RPAD];
__device__ int      g_tgt[RPAD];
__device__ float    g_pm[RPAD * NTMAX];
__device__ float    g_ps[RPAD * NTMAX];
__device__ float    g_rownll[RPAD];

__device__ __forceinline__ float neg_inf() { return __int_as_float(0xff800000u); }

// ---------------------------------------------------------------------------
// P0: scalars — W, flag, threshold, wf-uniformity, cutoff, seq dtype sniff
// ---------------------------------------------------------------------------
__global__ void k_p0(const float* __restrict__ w, const int* __restrict__ seq32) {
    int tid = threadIdx.x;
    float wf = w[1 + tid];
    float s = wf, mn = wf, mx = wf;
    #pragma unroll
    for (int o = 16; o; o >>= 1) {
        s  += __shfl_down_sync(0xffffffffu, s, o);
        mn  = fminf(mn, __shfl_down_sync(0xffffffffu, mn, o));
        mx  = fmaxf(mx, __shfl_down_sync(0xffffffffu, mx, o));
    }
    __shared__ float ssum[8], smin[8], smax[8];
    if ((tid & 31) == 0) { ssum[tid >> 5] = s; smin[tid >> 5] = mn; smax[tid >> 5] = mx; }
    __syncthreads();
    if (tid == 0) {
        float S = 0.f, MN = 3.0e38f, MX = -3.0e38f;
        #pragma unroll
        for (int i = 0; i < 8; i++) { S += ssum[i]; MN = fminf(MN, smin[i]); MX = fmaxf(MX, smax[i]); }
        float w0 = w[0];
        Cfg c;
        c.w0 = w0; c.W = S; c.w0x2 = 2.0f * w0;
        c.flag = (w0 >= 0.f && MN >= 0.f) ? 1 : 0;
        c.thresh = w0 * S - 33.0f;
        c.wfc = MN;
        c.delta = w0 * MN;
        // hamming cutoff: terms with ham > 36/delta are negligible (rel < 2e-12)
        if (c.delta > 0.f) {
            float hf = 36.0f / c.delta;
            c.ihhi = (hf >= 256.f) ? 256 : (int)hf;
        } else {
            c.ihhi = 256;   // delta == 0 under pc-path guard: keep all
        }
        int is64 = 1;
        for (int i = 0; i < 32; i++)
            if (seq32[2 * i + 1] != 0) { is64 = 0; break; }
        c.sstride = is64 ? 2 : 1;
        g_cfg = c;
        // pc path requires: uniform wf, w0>=0, wf>=0 (=> delta>=0, max at ham=0
        // attained at v=u). Binarity of features ANDed in k_p1.
        g_use_pc = (MN == MX && c.flag) ? 1 : 0;
    }
}

// ---------------------------------------------------------------------------
// P1: bit-pack features via ballot; s_feat; binarity check
// ---------------------------------------------------------------------------
__global__ void k_p1(const int* __restrict__ feat, const float* __restrict__ w) {
    int v = blockIdx.x, f = threadIdx.x;
    int fv = feat[(size_t)v * FF + f];
    uint32_t word = __ballot_sync(0xffffffffu, fv != 0);
    if ((f & 31) == 0) g_Bbits[v * NW + (f >> 5)] = word;
    int ok = (fv == 0 || fv == 1);
    if (!__syncthreads_and(ok)) {
        if (f == 0) atomicAnd(&g_use_pc, 0);
    }
    float p = (float)fv * w[1 + f];
    #pragma unroll
    for (int o = 16; o; o >>= 1) p += __shfl_down_sync(0xffffffffu, p, o);
    __shared__ float sred[8];
    if ((f & 31) == 0) sred[f >> 5] = p;
    __syncthreads();
    if (f == 0) {
        float s2 = 0.f;
        #pragma unroll
        for (int i = 0; i < 8; i++) s2 += sred[i];
        g_sfeat[v] = s2;
    }
}

// ---------------------------------------------------------------------------
// P2: packed A bits; u indices; row bias; targets. grid RPAD x 256
// ---------------------------------------------------------------------------
__global__ void k_p2(const int* __restrict__ seq32,
                     const int* __restrict__ feat) {
    int r = blockIdx.x, f = threadIdx.x;
    if (r < RR) {
        int b = r / (LLEN - 1), t = r % (LLEN - 1);
        int st = g_cfg.sstride;
        int u = seq32[(b * LLEN + t) * st] & VMASK;
        int fv = feat[(size_t)u * FF + f];
        uint32_t word = __ballot_sync(0xffffffffu, fv != 0);
        if ((f & 31) == 0) g_Abits[r * NW + (f >> 5)] = word;
        if (f == 0) {
            g_useq[r] = u;
            g_rowbias[r] = g_cfg.w0 * (g_cfg.W - g_sfeat[u]);
            g_tgt[r] = seq32[(b * LLEN + t + 1) * st] & VMASK;
        }
    } else {
        uint32_t word = __ballot_sync(0xffffffffu, 0);
        if ((f & 31) == 0) g_Abits[r * NW + (f >> 5)] = word;
        if (f == 0) { g_useq[r] = 0; g_rowbias[r] = 0.f; g_tgt[r] = 0; }
    }
}

// ---------------------------------------------------------------------------
// Hamming GEMM with 4-word partial rejection + exp-table epilogue.
// Tile 128(m) x 64(n), 256 threads, 4x8 outputs/thread. grid (PCNT, MT).
// Lower bound: total ham >= partial ham over words 0..3. Terms with
// ham > ihhi are negligible; survivors (essentially only v==u) finish
// the remaining 4 words and gather from the exp table.
// ---------------------------------------------------------------------------
__global__ __launch_bounds__(256, 4) void k_pc() {
    if (!g_use_pc) return;
    __shared__ uint32_t sA[BM][NW];    // word idx ^ ((row>>2)&7)
    __shared__ uint32_t sB[PCN][NW];   // word idx ^ (row>>3)
    __shared__ float    tbl[257];
    __shared__ float    red[BM][8];

    const int tid = threadIdx.x;
    const int tx = tid & 7, ty = tid >> 3;
    const int n0 = blockIdx.x * PCN, m0 = blockIdx.y * BM;
    const Cfg c = g_cfg;
    const float delta = c.delta;
    const int   ihhi  = c.ihhi;

    tbl[tid] = __expf(-delta * (float)tid);
    if (tid == 0) tbl[256] = __expf(-delta * 256.f);

    {
        int r = tid >> 1, h = (tid & 1) << 2;
        int sw = (r >> 2) & 7;
        uint4 a = *(const uint4*)&g_Abits[(size_t)(m0 + r) * NW + h];
        sA[r][(h + 0) ^ sw] = a.x; sA[r][(h + 1) ^ sw] = a.y;
        sA[r][(h + 2) ^ sw] = a.z; sA[r][(h + 3) ^ sw] = a.w;
    }
    if (tid < 128) {
        int r = tid >> 1, h = (tid & 1) << 2;
        int sw = (r >> 3) & 7;
        uint4 b = *(const uint4*)&g_Bbits[(size_t)(n0 + r) * NW + h];
        sB[r][(h + 0) ^ sw] = b.x; sB[r][(h + 1) ^ sw] = b.y;
        sB[r][(h + 2) ^ sw] = b.z; sB[r][(h + 3) ^ sw] = b.w;
    }
    __syncthreads();

    int acc[4][8];
    #pragma unroll
    for (int i = 0; i < 4; i++)
        #pragma unroll
        for (int j = 0; j < 8; j++) acc[i][j] = 0;

    const int swa = ty & 7;
    // partial hamming over words 0..3
    #pragma unroll
    for (int w = 0; w < 4; w++) {
        uint32_t av[4], bv[8];
        #pragma unroll
        for (int i = 0; i < 4; i++) av[i] = sA[ty * 4 + i][w ^ swa];
        #pragma unroll
        for (int j = 0; j < 8; j++) bv[j] = sB[tx * 8 + j][w ^ tx];
        #pragma unroll
        for (int i = 0; i < 4; i++)
            #pragma unroll
            for (int j = 0; j < 8; j++)
                acc[i][j] += __popc(av[i] ^ bv[j]);
    }

    // per-thread min partial -> single rare branch
    int hmin = acc[0][0];
    #pragma unroll
    for (int i = 0; i < 4; i++)
        #pragma unroll
        for (int j = 0; j < 8; j++) hmin = min(hmin, acc[i][j]);

    float s[4] = {0.f, 0.f, 0.f, 0.f};
    if (hmin <= ihhi) {
        #pragma unroll
        for (int i = 0; i < 4; i++) {
            #pragma unroll
            for (int j = 0; j < 8; j++) {
                if (acc[i][j] <= ihhi) {
                    int h = acc[i][j];
                    #pragma unroll
                    for (int w = 4; w < 8; w++)
                        h += __popc(sA[ty * 4 + i][w ^ swa] ^ sB[tx * 8 + j][w ^ tx]);
                    s[i] += tbl[h];
                }
            }
        }
    }
    #pragma unroll
    for (int i = 0; i < 4; i++) red[ty * 4 + i][tx] = s[i];
    __syncthreads();

    if (tid < BM) {
        float ss = 0.f;
        #pragma unroll
        for (int k = 0; k < 8; k++) ss += red[tid][k];
        g_pm[(size_t)(m0 + tid) * NTMAX + blockIdx.x] = delta * 256.f;  // attained at v=u
        g_ps[(size_t)(m0 + tid) * NTMAX + blockIdx.x] = ss;
    }
}

// ---------------------------------------------------------------------------
// fp32 SIMT fallback GEMM, converts from raw feat/w on the fly.
// Runs only if !g_use_pc. grid (NT, MT).
// ---------------------------------------------------------------------------
__global__ __launch_bounds__(256, 2) void k_gemm(const int* __restrict__ feat,
                                                 const float* __restrict__ w) {
    if (g_use_pc) return;
    __shared__ float As[KC][BM];
    __shared__ float Bs[KC][BN];
    __shared__ float red_m[BM][16];
    __shared__ float red_s[BM][16];

    const int tid = threadIdx.x;
    const int tx = tid & 15, ty = tid >> 4;
    const int m0 = blockIdx.y * BM, n0 = blockIdx.x * BN;
    const int ldrow = tid >> 3;
    const int ldc   = (tid & 7) << 2;

    float acc[8][8];
    #pragma unroll
    for (int i = 0; i < 8; i++)
        #pragma unroll
        for (int j = 0; j < 8; j++) acc[i][j] = 0.f;

    for (int k0 = 0; k0 < FF; k0 += KC) {
        float w0c = w[1 + k0 + ldc + 0], w1c = w[1 + k0 + ldc + 1];
        float w2c = w[1 + k0 + ldc + 2], w3c = w[1 + k0 + ldc + 3];
        #pragma unroll
        for (int q = 0; q < 4; q++) {
            int row = ldrow + q * 32;
            int ua = g_useq[m0 + row];
            int4 a = *(const int4*)&feat[(size_t)ua * FF + k0 + ldc];
            As[ldc + 0][row] = w0c * (float)a.x; As[ldc + 1][row] = w1c * (float)a.y;
            As[ldc + 2][row] = w2c * (float)a.z; As[ldc + 3][row] = w3c * (float)a.w;
            int4 b = *(const int4*)&feat[(size_t)(n0 + row) * FF + k0 + ldc];
            Bs[ldc + 0][row] = (float)b.x; Bs[ldc + 1][row] = (float)b.y;
            Bs[ldc + 2][row] = (float)b.z; Bs[ldc + 3][row] = (float)b.w;
        }
        __syncthreads();
        #pragma unroll
        for (int k = 0; k < KC; k++) {
            float4 a0 = *(const float4*)&As[k][ty * 8];
            float4 a1 = *(const float4*)&As[k][ty * 8 + 4];
            float4 b0 = *(const float4*)&Bs[k][tx * 8];
            float4 b1 = *(const float4*)&Bs[k][tx * 8 + 4];
            float av[8] = {a0.x, a0.y, a0.z, a0.w, a1.x, a1.y, a1.z, a1.w};
            float bv[8] = {b0.x, b0.y, b0.z, b0.w, b1.x, b1.y, b1.z, b1.w};
            #pragma unroll
            for (int i = 0; i < 8; i++)
                #pragma unroll
                for (int j = 0; j < 8; j++)
                    acc[i][j] = fmaf(av[i], bv[j], acc[i][j]);
        }
        __syncthreads();
    }

    Cfg c = g_cfg;
    float sv[8];
    #pragma unroll
    for (int j = 0; j < 8; j++) sv[j] = g_sfeat[n0 + tx * 8 + j];

    #pragma unroll
    for (int i = 0; i < 8; i++) {
        int m = ty * 8 + i;
        float rb = g_rowbias[m0 + m];
        float mi = neg_inf(), si = 0.f;
        #pragma unroll
        for (int j = 0; j < 8; j++) {
            float x = c.w0x2 * acc[i][j] - c.w0 * sv[j] + rb;
            if (!c.flag || x > c.thresh) {
                if (x > mi) { si = si * __expf(mi - x) + 1.0f; mi = x; }
                else        { si += __expf(x - mi); }
            }
        }
        red_m[m][tx] = mi;
        red_s[m][tx] = si;
    }
    __syncthreads();

    if (tid < BM) {
        float mm = neg_inf(), ss = 0.f;
        #pragma unroll
        for (int k = 0; k < 16; k++) {
            float mk = red_m[tid][k], sk = red_s[tid][k];
            if (sk > 0.f) {
                if (mk > mm) { ss = ss * __expf(mm - mk) + sk; mm = mk; }
                else         { ss += sk * __expf(mk - mm); }
            }
        }
        g_pm[(size_t)(m0 + tid) * NTMAX + blockIdx.x] = mm;
        g_ps[(size_t)(m0 + tid) * NTMAX + blockIdx.x] = ss;
    }
}

// ---------------------------------------------------------------------------
// Final stage 1: one warp per row -> per-row NLL. grid 63 x 1024 threads.
// ---------------------------------------------------------------------------
__global__ void k_final1(const int* __restrict__ feat, const float* __restrict__ w) {
    int tid = threadIdx.x, lane = tid & 31, wid = tid >> 5;
    int r = blockIdx.x * 32 + wid;
    if (r >= RR) return;

    int use_pc = g_use_pc;
    int ntiles = use_pc ? PCNT : NT;
    float mm = neg_inf(), ss = 0.f;
    for (int k = lane; k < ntiles; k += 32) {
        float mk = g_pm[(size_t)r * NTMAX + k], sk = g_ps[(size_t)r * NTMAX + k];
        if (sk > 0.f) {
            if (mk > mm) { ss = ss * __expf(mm - mk) + sk; mm = mk; }
            else         { ss += sk * __expf(mk - mm); }
        }
    }
    #pragma unroll
    for (int o = 16; o; o >>= 1) {
        float mo = __shfl_down_sync(0xffffffffu, mm, o);
        float so = __shfl_down_sync(0xffffffffu, ss, o);
        if (so > 0.f) {
            if (mo > mm) { ss = ss * __expf(mm - mo) + so; mm = mo; }
            else         { ss += so * __expf(mo - mm); }
        }
    }
    int tg = g_tgt[r];
    float xt;
    if (use_pc) {
        int h = (lane < NW) ? __popc(g_Abits[r * NW + lane] ^ g_Bbits[tg * NW + lane]) : 0;
        #pragma unroll
        for (int o = 16; o; o >>= 1) h += __shfl_down_sync(0xffffffffu, h, o);
        xt = g_cfg.delta * (256.f - (float)h);
    } else {
        int u = g_useq[r];
        float dot = 0.f;
        #pragma unroll
        for (int q = 0; q < 2; q++) {
            int f0 = q * 128 + lane * 4;
            int4 a = *(const int4*)&feat[(size_t)u  * FF + f0];
            int4 b = *(const int4*)&feat[(size_t)tg * FF + f0];
            dot += w[1 + f0 + 0] * (float)(a.x * b.x) + w[1 + f0 + 1] * (float)(a.y * b.y)
                 + w[1 + f0 + 2] * (float)(a.z * b.z) + w[1 + f0 + 3] * (float)(a.w * b.w);
        }
        #pragma unroll
        for (int o = 16; o; o >>= 1) dot += __shfl_down_sync(0xffffffffu, dot, o);
        xt = g_cfg.w0x2 * dot - g_cfg.w0 * g_sfeat[tg] + g_rowbias[r];
    }
    if (lane == 0) {
        g_rownll[r] = (mm + logf(ss)) - xt;
    }
}

// ---------------------------------------------------------------------------
// Final stage 2: deterministic tree-sum of row NLLs.
// ---------------------------------------------------------------------------
__global__ void k_final2(float* __restrict__ out) {
    __shared__ float red[1024];
    int tid = threadIdx.x;
    float v = 0.f;
    if (tid < RR)        v += g_rownll[tid];
    if (tid + 1024 < RR) v += g_rownll[tid + 1024];
    red[tid] = v;
    __syncthreads();
    #pragma unroll
    for (int s = 512; s > 0; s >>= 1) {
        if (tid < s) red[tid] += red[tid + s];
        __syncthreads();
    }
    if (tid == 0) out[0] = red[0] + (float)BBATCH * logf((float)VV);
}

// ---------------------------------------------------------------------------
extern "C" void kernel_launch(void* const* d_in, const int* in_sizes, int n_in,
                              void* d_out, int out_size) {
    const float* w    = 0;
    const int*   feat = 0;
    const int*   seq  = 0;
    for (int i = 0; i < n_in; i++) {
        if      (in_sizes[i] == FF + 1)        w    = (const float*)d_in[i];
        else if (in_sizes[i] == VV * FF)       feat = (const int*)d_in[i];
        else if (in_sizes[i] == BBATCH * LLEN) seq  = (const int*)d_in[i];
    }
    if (!w || !feat || !seq) {
        w    = (const float*)d_in[0];
        feat = (const int*)d_in[1];
        seq  = (const int*)d_in[2];
    }

    k_p0<<<1, 256>>>(w, seq);
    k_p1<<<VV, 256>>>(feat, w);
    k_p2<<<RPAD, 256>>>(seq, feat);
    k_pc<<<dim3(PCNT, MT), 256>>>();
    k_gemm<<<dim3(NT, MT), 256>>>(feat, w);
    k_final1<<<63, 1024>>>(feat, w);
    k_final2<<<1, 1024>>>((float*)d_out);
}

// round 8
// speedup vs baseline: 10.4368x; 1.2255x over previous
#include <cuda_runtime.h>
#include <math.h>
#include <stdint.h>

// Problem constants (V=8192, F=256, B=32, L=64)
#define VV     8192
#define FF     256
#define BBATCH 32
#define LLEN   64
#define RR     2016
#define RPAD   2048
#define BM     128
#define BN     128
#define KC     32
#define NW     8           // 256 bits = 8 x u32 words
#define NT     64          // fallback n-tiles (BN=128)
#define PCN    64          // pc path: n-cols per CTA
#define PCNT   128         // pc path: n-tiles
#define NTMAX  128         // pm/ps stride
#define MT     16          // m-tiles
#define VMASK  (VV - 1)

struct Cfg { float w0, W, w0x2, thresh, wfc, delta; int flag, ihhi; };

__device__ Cfg      g_cfg;
__device__ int      g_use_pc = 1;   // reset to 1 by k_fin each call
__device__ int      g_ticket = 0;   // reset to 0 by k_fin each call
__device__ uint32_t g_Bbits[VV * NW];
__device__ uint32_t g_Abits[RPAD * NW];
__device__ int      g_useq[RPAD];
__device__ int      g_tgt[RPAD];
__device__ float    g_sfeat[VV];
__device__ float    g_pm[RPAD * NTMAX];
__device__ float    g_ps[RPAD * NTMAX];
__device__ float    g_rownll[RPAD];

__device__ __forceinline__ float neg_inf() { return __int_as_float(0xff800000u); }

// ---------------------------------------------------------------------------
// PREP: grid = VV + RPAD blocks, 256 threads.
// Blocks [0, VV):    pack B bits, s_feat, binarity check; block 0 also cfg.
// Blocks [VV, +RPAD): pack A bits, useq, tgt (local seq-dtype sniff).
// ---------------------------------------------------------------------------
__global__ void k_prep(const int* __restrict__ feat, const float* __restrict__ w,
                       const int* __restrict__ seq32) {
    const int bid = blockIdx.x, f = threadIdx.x;

    if (bid < VV) {
        const int v = bid;
        int fv = feat[(size_t)v * FF + f];
        uint32_t word = __ballot_sync(0xffffffffu, fv != 0);
        if ((f & 31) == 0) g_Bbits[v * NW + (f >> 5)] = word;
        int ok = (fv == 0 || fv == 1);
        if (!__syncthreads_and(ok)) {
            if (f == 0) atomicAnd(&g_use_pc, 0);
        }
        float p = (float)fv * w[1 + f];
        #pragma unroll
        for (int o = 16; o; o >>= 1) p += __shfl_down_sync(0xffffffffu, p, o);
        __shared__ float sred[8];
        if ((f & 31) == 0) sred[f >> 5] = p;
        __syncthreads();
        if (f == 0) {
            float s2 = 0.f;
            #pragma unroll
            for (int i = 0; i < 8; i++) s2 += sred[i];
            g_sfeat[v] = s2;
        }

        if (v == 0) {   // block 0: scalar config
            float wf = w[1 + f];
            float s = wf, mn = wf, mx = wf;
            #pragma unroll
            for (int o = 16; o; o >>= 1) {
                s  += __shfl_down_sync(0xffffffffu, s, o);
                mn  = fminf(mn, __shfl_down_sync(0xffffffffu, mn, o));
                mx  = fmaxf(mx, __shfl_down_sync(0xffffffffu, mx, o));
            }
            __shared__ float ssum[8], smin[8], smax[8];
            if ((f & 31) == 0) { ssum[f >> 5] = s; smin[f >> 5] = mn; smax[f >> 5] = mx; }
            __syncthreads();
            if (f == 0) {
                float S = 0.f, MN = 3.0e38f, MX = -3.0e38f;
                #pragma unroll
                for (int i = 0; i < 8; i++) {
                    S += ssum[i]; MN = fminf(MN, smin[i]); MX = fmaxf(MX, smax[i]);
                }
                float w0 = w[0];
                Cfg c;
                c.w0 = w0; c.W = S; c.w0x2 = 2.0f * w0;
                c.flag = (w0 >= 0.f && MN >= 0.f) ? 1 : 0;
                c.thresh = w0 * S - 33.0f;
                c.wfc = MN;
                c.delta = w0 * MN;
                if (c.delta > 0.f) {
                    float hf = 36.0f / c.delta;
                    c.ihhi = (hf >= 256.f) ? 256 : (int)hf;
                } else {
                    c.ihhi = 256;
                }
                g_cfg = c;
                // pc path requires uniform wf and w0,wf >= 0
                atomicAnd(&g_use_pc, (MN == MX && c.flag) ? 1 : 0);
            }
        }
    } else {
        const int r = bid - VV;
        // local seq dtype sniff: int64 values < 2^31 -> all odd words zero
        __shared__ int s_st;
        if (f < 32) {
            int odd = seq32[2 * f + 1];
            uint32_t nz = __ballot_sync(0xffffffffu, odd != 0);
            if (f == 0) s_st = (nz == 0) ? 2 : 1;
        }
        __syncthreads();
        const int st = s_st;

        if (r < RR) {
            int b = r / (LLEN - 1), t = r % (LLEN - 1);
            int u = seq32[(b * LLEN + t) * st] & VMASK;
            int fv = feat[(size_t)u * FF + f];
            uint32_t word = __ballot_sync(0xffffffffu, fv != 0);
            if ((f & 31) == 0) g_Abits[r * NW + (f >> 5)] = word;
            if (f == 0) {
                g_useq[r] = u;
                g_tgt[r] = seq32[(b * LLEN + t + 1) * st] & VMASK;
            }
        } else {
            uint32_t word = __ballot_sync(0xffffffffu, 0);
            if ((f & 31) == 0) g_Abits[r * NW + (f >> 5)] = word;
            if (f == 0) { g_useq[r] = 0; g_tgt[r] = 0; }
        }
    }
}

// ---------------------------------------------------------------------------
// MAIN: grid (PCNT, MT), 256 threads. Union smem (32 KB).
// pc path:  hamming GEMM w/ 4-word rejection + exp-table; writes ps only.
// fallback: fp32 SIMT GEMM (blocks with bx < NT) + online LSE; writes pm+ps.
// ---------------------------------------------------------------------------
__global__ __launch_bounds__(256, 4) void k_main(const int* __restrict__ feat,
                                                 const float* __restrict__ w) {
    __shared__ __align__(16) char U[32768];
    const int tid = threadIdx.x;
    const Cfg c = g_cfg;

    if (g_use_pc) {
        uint32_t (*sA)[NW] = (uint32_t(*)[NW])(U);            // 4096 B
        uint32_t (*sB)[NW] = (uint32_t(*)[NW])(U + 4096);     // 2048 B
        float* tbl         = (float*)(U + 6144);              // 1028 B
        float (*red)[8]    = (float(*)[8])(U + 7200);         // 4096 B

        const int tx = tid & 7, ty = tid >> 3;
        const int n0 = blockIdx.x * PCN, m0 = blockIdx.y * BM;
        const float delta = c.delta;
        const int   ihhi  = c.ihhi;

        tbl[tid] = __expf(-delta * (float)tid);
        if (tid == 0) tbl[256] = __expf(-delta * 256.f);

        {
            int r = tid >> 1, h = (tid & 1) << 2;
            int sw = (r >> 2) & 7;
            uint4 a = *(const uint4*)&g_Abits[(size_t)(m0 + r) * NW + h];
            sA[r][(h + 0) ^ sw] = a.x; sA[r][(h + 1) ^ sw] = a.y;
            sA[r][(h + 2) ^ sw] = a.z; sA[r][(h + 3) ^ sw] = a.w;
        }
        if (tid < 128) {
            int r = tid >> 1, h = (tid & 1) << 2;
            int sw = (r >> 3) & 7;
            uint4 b = *(const uint4*)&g_Bbits[(size_t)(n0 + r) * NW + h];
            sB[r][(h + 0) ^ sw] = b.x; sB[r][(h + 1) ^ sw] = b.y;
            sB[r][(h + 2) ^ sw] = b.z; sB[r][(h + 3) ^ sw] = b.w;
        }
        __syncthreads();

        int acc[4][8];
        #pragma unroll
        for (int i = 0; i < 4; i++)
            #pragma unroll
            for (int j = 0; j < 8; j++) acc[i][j] = 0;

        const int swa = ty & 7;
        #pragma unroll
        for (int wi = 0; wi < 4; wi++) {
            uint32_t av[4], bv[8];
            #pragma unroll
            for (int i = 0; i < 4; i++) av[i] = sA[ty * 4 + i][wi ^ swa];
            #pragma unroll
            for (int j = 0; j < 8; j++) bv[j] = sB[tx * 8 + j][wi ^ tx];
            #pragma unroll
            for (int i = 0; i < 4; i++)
                #pragma unroll
                for (int j = 0; j < 8; j++)
                    acc[i][j] += __popc(av[i] ^ bv[j]);
        }

        int hmin = acc[0][0];
        #pragma unroll
        for (int i = 0; i < 4; i++)
            #pragma unroll
            for (int j = 0; j < 8; j++) hmin = min(hmin, acc[i][j]);

        float s[4] = {0.f, 0.f, 0.f, 0.f};
        if (hmin <= ihhi) {
            #pragma unroll
            for (int i = 0; i < 4; i++) {
                #pragma unroll
                for (int j = 0; j < 8; j++) {
                    if (acc[i][j] <= ihhi) {
                        int h = acc[i][j];
                        #pragma unroll
                        for (int wi = 4; wi < 8; wi++)
                            h += __popc(sA[ty * 4 + i][wi ^ swa] ^ sB[tx * 8 + j][wi ^ tx]);
                        s[i] += tbl[h];
                    }
                }
            }
        }
        #pragma unroll
        for (int i = 0; i < 4; i++) red[ty * 4 + i][tx] = s[i];
        __syncthreads();

        if (tid < BM) {
            float ss = 0.f;
            #pragma unroll
            for (int k = 0; k < 8; k++) ss += red[tid][k];
            g_ps[(size_t)(m0 + tid) * NTMAX + blockIdx.x] = ss;
        }
        return;
    }

    // ---------------- fallback fp32 GEMM ----------------
    if (blockIdx.x >= NT) return;
    float (*As)[BM] = (float(*)[BM])(U);            // 16 KB
    float (*Bs)[BN] = (float(*)[BN])(U + 16384);    // 16 KB

    const int tx = tid & 15, ty = tid >> 4;
    const int m0 = blockIdx.y * BM, n0 = blockIdx.x * BN;
    const int ldrow = tid >> 3;
    const int ldc   = (tid & 7) << 2;

    float acc[8][8];
    #pragma unroll
    for (int i = 0; i < 8; i++)
        #pragma unroll
        for (int j = 0; j < 8; j++) acc[i][j] = 0.f;

    for (int k0 = 0; k0 < FF; k0 += KC) {
        float w0c = w[1 + k0 + ldc + 0], w1c = w[1 + k0 + ldc + 1];
        float w2c = w[1 + k0 + ldc + 2], w3c = w[1 + k0 + ldc + 3];
        #pragma unroll
        for (int q = 0; q < 4; q++) {
            int row = ldrow + q * 32;
            int ua = g_useq[m0 + row];
            int4 a = *(const int4*)&feat[(size_t)ua * FF + k0 + ldc];
            As[ldc + 0][row] = w0c * (float)a.x; As[ldc + 1][row] = w1c * (float)a.y;
            As[ldc + 2][row] = w2c * (float)a.z; As[ldc + 3][row] = w3c * (float)a.w;
            int4 b = *(const int4*)&feat[(size_t)(n0 + row) * FF + k0 + ldc];
            Bs[ldc + 0][row] = (float)b.x; Bs[ldc + 1][row] = (float)b.y;
            Bs[ldc + 2][row] = (float)b.z; Bs[ldc + 3][row] = (float)b.w;
        }
        __syncthreads();
        #pragma unroll
        for (int k = 0; k < KC; k++) {
            float4 a0 = *(const float4*)&As[k][ty * 8];
            float4 a1 = *(const float4*)&As[k][ty * 8 + 4];
            float4 b0 = *(const float4*)&Bs[k][tx * 8];
            float4 b1 = *(const float4*)&Bs[k][tx * 8 + 4];
            float av[8] = {a0.x, a0.y, a0.z, a0.w, a1.x, a1.y, a1.z, a1.w};
            float bv[8] = {b0.x, b0.y, b0.z, b0.w, b1.x, b1.y, b1.z, b1.w};
            #pragma unroll
            for (int i = 0; i < 8; i++)
                #pragma unroll
                for (int j = 0; j < 8; j++)
                    acc[i][j] = fmaf(av[i], bv[j], acc[i][j]);
        }
        __syncthreads();
    }

    // reuse As/Bs region for reductions (all reads of As/Bs are done)
    float (*red_m)[16] = (float(*)[16])(U);          // 8 KB
    float (*red_s)[16] = (float(*)[16])(U + 8192);   // 8 KB

    float sv[8];
    #pragma unroll
    for (int j = 0; j < 8; j++) sv[j] = g_sfeat[n0 + tx * 8 + j];

    #pragma unroll
    for (int i = 0; i < 8; i++) {
        int m = ty * 8 + i;
        int uu = g_useq[m0 + m];
        float rb = c.w0 * (c.W - g_sfeat[uu]);
        float mi = neg_inf(), si = 0.f;
        #pragma unroll
        for (int j = 0; j < 8; j++) {
            float x = c.w0x2 * acc[i][j] - c.w0 * sv[j] + rb;
            if (!c.flag || x > c.thresh) {
                if (x > mi) { si = si * __expf(mi - x) + 1.0f; mi = x; }
                else        { si += __expf(x - mi); }
            }
        }
        red_m[m][tx] = mi;
        red_s[m][tx] = si;
    }
    __syncthreads();

    if (tid < BM) {
        float mm = neg_inf(), ss = 0.f;
        #pragma unroll
        for (int k = 0; k < 16; k++) {
            float mk = red_m[tid][k], sk = red_s[tid][k];
            if (sk > 0.f) {
                if (mk > mm) { ss = ss * __expf(mm - mk) + sk; mm = mk; }
                else         { ss += sk * __expf(mk - mm); }
            }
        }
        g_pm[(size_t)(m0 + tid) * NTMAX + blockIdx.x] = mm;
        g_ps[(size_t)(m0 + tid) * NTMAX + blockIdx.x] = ss;
    }
}

// ---------------------------------------------------------------------------
// FIN: grid 63 x 1024 (one warp per row). Last block (ticket) reduces all
// row NLLs in fixed order, writes the scalar, and resets globals for replay.
// ---------------------------------------------------------------------------
__global__ void k_fin(const int* __restrict__ feat, const float* __restrict__ w,
                      float* __restrict__ out) {
    __shared__ int s_last;
    int tid = threadIdx.x, lane = tid & 31, wid = tid >> 5;
    int r = blockIdx.x * 32 + wid;
    const int use_pc = g_use_pc;

    {
        float lse;
        int tg = g_tgt[r];
        float xt;
        if (use_pc) {
            float s = 0.f;
            #pragma unroll
            for (int q = 0; q < 4; q++) s += g_ps[(size_t)r * NTMAX + lane + 32 * q];
            #pragma unroll
            for (int o = 16; o; o >>= 1) s += __shfl_down_sync(0xffffffffu, s, o);
            lse = g_cfg.delta * 256.f + logf(s);
            int h = (lane < NW) ? __popc(g_Abits[r * NW + lane] ^ g_Bbits[tg * NW + lane]) : 0;
            #pragma unroll
            for (int o = 16; o; o >>= 1) h += __shfl_down_sync(0xffffffffu, h, o);
            xt = g_cfg.delta * (256.f - (float)h);
        } else {
            float mm = neg_inf(), ss = 0.f;
            #pragma unroll
            for (int q = 0; q < 2; q++) {
                int k = lane + 32 * q;
                float mk = g_pm[(size_t)r * NTMAX + k], sk = g_ps[(size_t)r * NTMAX + k];
                if (sk > 0.f) {
                    if (mk > mm) { ss = ss * __expf(mm - mk) + sk; mm = mk; }
                    else         { ss += sk * __expf(mk - mm); }
                }
            }
            #pragma unroll
            for (int o = 16; o; o >>= 1) {
                float mo = __shfl_down_sync(0xffffffffu, mm, o);
                float so = __shfl_down_sync(0xffffffffu, ss, o);
                if (so > 0.f) {
                    if (mo > mm) { ss = ss * __expf(mm - mo) + so; mm = mo; }
                    else         { ss += so * __expf(mo - mm); }
                }
            }
            lse = mm + logf(ss);
            int u = g_useq[r];
            float dot = 0.f;
            #pragma unroll
            for (int q = 0; q < 2; q++) {
                int f0 = q * 128 + lane * 4;
                int4 a = *(const int4*)&feat[(size_t)u  * FF + f0];
                int4 b = *(const int4*)&feat[(size_t)tg * FF + f0];
                dot += w[1 + f0 + 0] * (float)(a.x * b.x) + w[1 + f0 + 1] * (float)(a.y * b.y)
                     + w[1 + f0 + 2] * (float)(a.z * b.z) + w[1 + f0 + 3] * (float)(a.w * b.w);
            }
            #pragma unroll
            for (int o = 16; o; o >>= 1) dot += __shfl_down_sync(0xffffffffu, dot, o);
            float rb = g_cfg.w0 * (g_cfg.W - g_sfeat[u]);
            xt = g_cfg.w0x2 * dot - g_cfg.w0 * g_sfeat[tg] + rb;
        }
        if (lane == 0) g_rownll[r] = lse - xt;
    }

    // last-block reduction (deterministic: one block, fixed order)
    __syncthreads();
    if (tid == 0) {
        __threadfence();
        int t = atomicAdd(&g_ticket, 1);
        s_last = (t == gridDim.x - 1);
    }
    __syncthreads();
    if (s_last) {
        __threadfence();
        __shared__ float red[1024];
        float v = 0.f;
        if (tid < RR)        v += g_rownll[tid];
        if (tid + 1024 < RR) v += g_rownll[tid + 1024];
        red[tid] = v;
        __syncthreads();
        #pragma unroll
        for (int s = 512; s > 0; s >>= 1) {
            if (tid < s) red[tid] += red[tid + s];
            __syncthreads();
        }
        if (tid == 0) {
            out[0] = red[0] + (float)BBATCH * logf((float)VV);
            g_ticket = 0;     // reset for next graph replay
            g_use_pc = 1;
        }
    }
}

// ---------------------------------------------------------------------------
extern "C" void kernel_launch(void* const* d_in, const int* in_sizes, int n_in,
                              void* d_out, int out_size) {
    const float* w    = 0;
    const int*   feat = 0;
    const int*   seq  = 0;
    for (int i = 0; i < n_in; i++) {
        if      (in_sizes[i] == FF + 1)        w    = (const float*)d_in[i];
        else if (in_sizes[i] == VV * FF)       feat = (const int*)d_in[i];
        else if (in_sizes[i] == BBATCH * LLEN) seq  = (const int*)d_in[i];
    }
    if (!w || !feat || !seq) {
        w    = (const float*)d_in[0];
        feat = (const int*)d_in[1];
        seq  = (const int*)d_in[2];
    }

    k_prep<<<VV + RPAD, 256>>>(feat, w, seq);
    k_main<<<dim3(PCNT, MT), 256>>>(feat, w);
    k_fin<<<63, 1024>>>(feat, w, (float*)d_out);
}

// round 10
// speedup vs baseline: 12.1305x; 1.1623x over previous
#include <cuda_runtime.h>
#include <math.h>
#include <stdint.h>

// Problem constants (V=8192, F=256, B=32, L=64)
#define VV     8192
#define FF     256
#define BBATCH 32
#define LLEN   64
#define RR     2016
#define RPAD   2048
#define BM     128
#define BN     128
#define KC     32
#define NW     8           // 256 bits = 8 x u32 words
#define NT     64          // fallback n-tiles (BN=128)
#define PCN    64          // pc path: n-cols per CTA
#define PCNT   128         // pc path: n-tiles
#define NTMAX  128         // pm/ps stride
#define MT     16          // m-tiles
#define VMASK  (VV - 1)
#define PREPB  (VV / 8)    // 1024 packing blocks; block PREPB = cfg + seq

struct Cfg { float w0, W, w0x2, thresh, wfc, delta; int flag, ihhi; };

__device__ Cfg      g_cfg;
__device__ int      g_use_pc = 1;   // reset by k_fin each call
__device__ int      g_ticket = 0;   // reset by k_fin each call
__device__ uint32_t g_Bbits[VV * NW];
__device__ int      g_useq[RPAD];
__device__ int      g_tgt[RPAD];
__device__ float    g_sfeat[VV];
__device__ float    g_pm[RPAD * NTMAX];
__device__ float    g_ps[RPAD * NTMAX];
__device__ float    g_rownll[RPAD];

__device__ __forceinline__ float neg_inf() { return __int_as_float(0xff800000u); }

__device__ __forceinline__ uint32_t nib_of(int4 x) {
    return (uint32_t)(x.x != 0) | ((uint32_t)(x.y != 0) << 1)
         | ((uint32_t)(x.z != 0) << 2) | ((uint32_t)(x.w != 0) << 3);
}
__device__ __forceinline__ int bin_ok(int4 x) {
    return ((x.x | x.y | x.z | x.w) & ~1) == 0 &&
           x.x >= 0 && x.y >= 0 && x.z >= 0 && x.w >= 0;
}

// ---------------------------------------------------------------------------
// PREP: grid = PREPB + 1 blocks, 256 threads.
// Blocks [0, PREPB): pack 8 vocab rows each (int4 loads, shfl-OR packing),
//                    s_feat, binarity check.
// Block PREPB:       scalar cfg + seq decode (useq/tgt, dtype sniff).
// ---------------------------------------------------------------------------
__global__ void k_prep(const int* __restrict__ feat, const float* __restrict__ w,
                       const int* __restrict__ seq32) {
    const int bid = blockIdx.x, tid = threadIdx.x;

    if (bid < PREPB) {
        const int grp = tid >> 6;            // 0..3
        const int t   = tid & 63;            // thread within row (4 feats each)
        const int v0  = bid * 8 + grp;       // first row
        const int v1  = v0 + 4;              // second row

        int4 x0 = *(const int4*)&feat[(size_t)v0 * FF + t * 4];
        int4 x1 = *(const int4*)&feat[(size_t)v1 * FF + t * 4];
        // NOTE: w+1 is only 4B-aligned -> scalar loads (no float4!)
        float wx = w[1 + t * 4 + 0], wy = w[1 + t * 4 + 1];
        float wz = w[1 + t * 4 + 2], ww = w[1 + t * 4 + 3];

        // --- bit packing: nibble -> OR-reduce across groups of 8 lanes ---
        uint32_t n0 = nib_of(x0) << ((t & 7) * 4);
        uint32_t n1 = nib_of(x1) << ((t & 7) * 4);
        #pragma unroll
        for (int o = 1; o < 8; o <<= 1) {
            n0 |= __shfl_xor_sync(0xffffffffu, n0, o);
            n1 |= __shfl_xor_sync(0xffffffffu, n1, o);
        }
        if ((t & 7) == 0) {
            g_Bbits[v0 * NW + (t >> 3)] = n0;
            g_Bbits[v1 * NW + (t >> 3)] = n1;
        }

        // --- binarity ---
        int ok = bin_ok(x0) && bin_ok(x1);
        if (!__syncthreads_and(ok)) {
            if (tid == 0) atomicAnd(&g_use_pc, 0);
        }

        // --- s_feat: weighted row sums ---
        float p0 = wx * (float)x0.x + wy * (float)x0.y
                 + wz * (float)x0.z + ww * (float)x0.w;
        float p1 = wx * (float)x1.x + wy * (float)x1.y
                 + wz * (float)x1.z + ww * (float)x1.w;
        #pragma unroll
        for (int o = 16; o; o >>= 1) {
            p0 += __shfl_down_sync(0xffffffffu, p0, o);
            p1 += __shfl_down_sync(0xffffffffu, p1, o);
        }
        __shared__ float sred[8][2];
        if ((t & 31) == 0) {
            sred[grp][t >> 5] = p0;
            sred[grp + 4][t >> 5] = p1;
        }
        __syncthreads();
        if (tid < 8) g_sfeat[bid * 8 + tid] = sred[tid][0] + sred[tid][1];
        return;
    }

    // ------- tail block: scalar config + sequence decode -------
    {
        float wf = w[1 + tid];
        float s = wf, mn = wf, mx = wf;
        #pragma unroll
        for (int o = 16; o; o >>= 1) {
            s  += __shfl_down_sync(0xffffffffu, s, o);
            mn  = fminf(mn, __shfl_down_sync(0xffffffffu, mn, o));
            mx  = fmaxf(mx, __shfl_down_sync(0xffffffffu, mx, o));
        }
        __shared__ float ssum[8], smin[8], smax[8];
        __shared__ int s_st;
        if ((tid & 31) == 0) { ssum[tid >> 5] = s; smin[tid >> 5] = mn; smax[tid >> 5] = mx; }
        if (tid < 32) {
            int odd = seq32[2 * tid + 1];
            uint32_t nz = __ballot_sync(0xffffffffu, odd != 0);
            if (tid == 0) s_st = (nz == 0) ? 2 : 1;
        }
        __syncthreads();
        if (tid == 0) {
            float S = 0.f, MN = 3.0e38f, MX = -3.0e38f;
            #pragma unroll
            for (int i = 0; i < 8; i++) {
                S += ssum[i]; MN = fminf(MN, smin[i]); MX = fmaxf(MX, smax[i]);
            }
            float w0 = w[0];
            Cfg c;
            c.w0 = w0; c.W = S; c.w0x2 = 2.0f * w0;
            c.flag = (w0 >= 0.f && MN >= 0.f) ? 1 : 0;
            c.thresh = w0 * S - 33.0f;
            c.wfc = MN;
            c.delta = w0 * MN;
            if (c.delta > 0.f) {
                float hf = 36.0f / c.delta;
                c.ihhi = (hf >= 256.f) ? 256 : (int)hf;
            } else {
                c.ihhi = 256;
            }
            g_cfg = c;
            atomicAnd(&g_use_pc, (MN == MX && c.flag) ? 1 : 0);
        }
        const int st = s_st;
        #pragma unroll
        for (int it = 0; it < 8; it++) {
            int r = it * 256 + tid;
            if (r < RR) {
                int b = r / (LLEN - 1), t2 = r % (LLEN - 1);
                g_useq[r] = seq32[(b * LLEN + t2) * st] & VMASK;
                g_tgt[r]  = seq32[(b * LLEN + t2 + 1) * st] & VMASK;
            } else {
                g_useq[r] = 0; g_tgt[r] = 0;
            }
        }
    }
}

// ---------------------------------------------------------------------------
// MAIN: grid (PCNT, MT), 256 threads. Union smem (32 KB).
// pc path:  hamming GEMM w/ 4-word rejection + exp-table; writes ps only.
//           A tile staged from g_Bbits via useq indirection.
// fallback: fp32 SIMT GEMM (blocks with bx < NT) + online LSE; writes pm+ps.
// ---------------------------------------------------------------------------
__global__ __launch_bounds__(256, 4) void k_main(const int* __restrict__ feat,
                                                 const float* __restrict__ w) {
    __shared__ __align__(16) char U[32768];
    const int tid = threadIdx.x;
    const Cfg c = g_cfg;

    if (g_use_pc) {
        uint32_t (*sA)[NW] = (uint32_t(*)[NW])(U);            // 4096 B
        uint32_t (*sB)[NW] = (uint32_t(*)[NW])(U + 4096);     // 2048 B
        float* tbl         = (float*)(U + 6144);              // 1028 B
        float (*red)[8]    = (float(*)[8])(U + 7200);         // 4096 B

        const int tx = tid & 7, ty = tid >> 3;
        const int n0 = blockIdx.x * PCN, m0 = blockIdx.y * BM;
        const float delta = c.delta;
        const int   ihhi  = c.ihhi;

        tbl[tid] = __expf(-delta * (float)tid);
        if (tid == 0) tbl[256] = __expf(-delta * 256.f);

        {
            int r = tid >> 1, h = (tid & 1) << 2;
            int sw = (r >> 2) & 7;
            int u = g_useq[m0 + r];
            uint4 a = *(const uint4*)&g_Bbits[(size_t)u * NW + h];
            sA[r][(h + 0) ^ sw] = a.x; sA[r][(h + 1) ^ sw] = a.y;
            sA[r][(h + 2) ^ sw] = a.z; sA[r][(h + 3) ^ sw] = a.w;
        }
        if (tid < 128) {
            int r = tid >> 1, h = (tid & 1) << 2;
            int sw = (r >> 3) & 7;
            uint4 b = *(const uint4*)&g_Bbits[(size_t)(n0 + r) * NW + h];
            sB[r][(h + 0) ^ sw] = b.x; sB[r][(h + 1) ^ sw] = b.y;
            sB[r][(h + 2) ^ sw] = b.z; sB[r][(h + 3) ^ sw] = b.w;
        }
        __syncthreads();

        int acc[4][8];
        #pragma unroll
        for (int i = 0; i < 4; i++)
            #pragma unroll
            for (int j = 0; j < 8; j++) acc[i][j] = 0;

        const int swa = ty & 7;
        #pragma unroll
        for (int wi = 0; wi < 4; wi++) {
            uint32_t av[4], bv[8];
            #pragma unroll
            for (int i = 0; i < 4; i++) av[i] = sA[ty * 4 + i][wi ^ swa];
            #pragma unroll
            for (int j = 0; j < 8; j++) bv[j] = sB[tx * 8 + j][wi ^ tx];
            #pragma unroll
            for (int i = 0; i < 4; i++)
                #pragma unroll
                for (int j = 0; j < 8; j++)
                    acc[i][j] += __popc(av[i] ^ bv[j]);
        }

        int hmin = acc[0][0];
        #pragma unroll
        for (int i = 0; i < 4; i++)
            #pragma unroll
            for (int j = 0; j < 8; j++) hmin = min(hmin, acc[i][j]);

        float s[4] = {0.f, 0.f, 0.f, 0.f};
        if (hmin <= ihhi) {
            #pragma unroll
            for (int i = 0; i < 4; i++) {
                #pragma unroll
                for (int j = 0; j < 8; j++) {
                    if (acc[i][j] <= ihhi) {
                        int h = acc[i][j];
                        #pragma unroll
                        for (int wi = 4; wi < 8; wi++)
                            h += __popc(sA[ty * 4 + i][wi ^ swa] ^ sB[tx * 8 + j][wi ^ tx]);
                        s[i] += tbl[h];
                    }
                }
            }
        }
        #pragma unroll
        for (int i = 0; i < 4; i++) red[ty * 4 + i][tx] = s[i];
        __syncthreads();

        if (tid < BM) {
            float ss = 0.f;
            #pragma unroll
            for (int k = 0; k < 8; k++) ss += red[tid][k];
            g_ps[(size_t)(m0 + tid) * NTMAX + blockIdx.x] = ss;
        }
        return;
    }

    // ---------------- fallback fp32 GEMM ----------------
    if (blockIdx.x >= NT) return;
    float (*As)[BM] = (float(*)[BM])(U);            // 16 KB
    float (*Bs)[BN] = (float(*)[BN])(U + 16384);    // 16 KB

    const int tx = tid & 15, ty = tid >> 4;
    const int m0 = blockIdx.y * BM, n0 = blockIdx.x * BN;
    const int ldrow = tid >> 3;
    const int ldc   = (tid & 7) << 2;

    float acc[8][8];
    #pragma unroll
    for (int i = 0; i < 8; i++)
        #pragma unroll
        for (int j = 0; j < 8; j++) acc[i][j] = 0.f;

    for (int k0 = 0; k0 < FF; k0 += KC) {
        float w0c = w[1 + k0 + ldc + 0], w1c = w[1 + k0 + ldc + 1];
        float w2c = w[1 + k0 + ldc + 2], w3c = w[1 + k0 + ldc + 3];
        #pragma unroll
        for (int q = 0; q < 4; q++) {
            int row = ldrow + q * 32;
            int ua = g_useq[m0 + row];
            int4 a = *(const int4*)&feat[(size_t)ua * FF + k0 + ldc];
            As[ldc + 0][row] = w0c * (float)a.x; As[ldc + 1][row] = w1c * (float)a.y;
            As[ldc + 2][row] = w2c * (float)a.z; As[ldc + 3][row] = w3c * (float)a.w;
            int4 b = *(const int4*)&feat[(size_t)(n0 + row) * FF + k0 + ldc];
            Bs[ldc + 0][row] = (float)b.x; Bs[ldc + 1][row] = (float)b.y;
            Bs[ldc + 2][row] = (float)b.z; Bs[ldc + 3][row] = (float)b.w;
        }
        __syncthreads();
        #pragma unroll
        for (int k = 0; k < KC; k++) {
            float4 a0 = *(const float4*)&As[k][ty * 8];
            float4 a1 = *(const float4*)&As[k][ty * 8 + 4];
            float4 b0 = *(const float4*)&Bs[k][tx * 8];
            float4 b1 = *(const float4*)&Bs[k][tx * 8 + 4];
            float av[8] = {a0.x, a0.y, a0.z, a0.w, a1.x, a1.y, a1.z, a1.w};
            float bv[8] = {b0.x, b0.y, b0.z, b0.w, b1.x, b1.y, b1.z, b1.w};
            #pragma unroll
            for (int i = 0; i < 8; i++)
                #pragma unroll
                for (int j = 0; j < 8; j++)
                    acc[i][j] = fmaf(av[i], bv[j], acc[i][j]);
        }
        __syncthreads();
    }

    float (*red_m)[16] = (float(*)[16])(U);          // reuse As/Bs region
    float (*red_s)[16] = (float(*)[16])(U + 8192);

    float sv[8];
    #pragma unroll
    for (int j = 0; j < 8; j++) sv[j] = g_sfeat[n0 + tx * 8 + j];

    #pragma unroll
    for (int i = 0; i < 8; i++) {
        int m = ty * 8 + i;
        int uu = g_useq[m0 + m];
        float rb = c.w0 * (c.W - g_sfeat[uu]);
        float mi = neg_inf(), si = 0.f;
        #pragma unroll
        for (int j = 0; j < 8; j++) {
            float x = c.w0x2 * acc[i][j] - c.w0 * sv[j] + rb;
            if (!c.flag || x > c.thresh) {
                if (x > mi) { si = si * __expf(mi - x) + 1.0f; mi = x; }
                else        { si += __expf(x - mi); }
            }
        }
        red_m[m][tx] = mi;
        red_s[m][tx] = si;
    }
    __syncthreads();

    if (tid < BM) {
        float mm = neg_inf(), ss = 0.f;
        #pragma unroll
        for (int k = 0; k < 16; k++) {
            float mk = red_m[tid][k], sk = red_s[tid][k];
            if (sk > 0.f) {
                if (mk > mm) { ss = ss * __expf(mm - mk) + sk; mm = mk; }
                else         { ss += sk * __expf(mk - mm); }
            }
        }
        g_pm[(size_t)(m0 + tid) * NTMAX + blockIdx.x] = mm;
        g_ps[(size_t)(m0 + tid) * NTMAX + blockIdx.x] = ss;
    }
}

// ---------------------------------------------------------------------------
// FIN: grid 63 x 1024 (one warp per row). Last block reduces row NLLs in
// fixed order, writes the scalar, resets globals for graph replay.
// ---------------------------------------------------------------------------
__global__ void k_fin(const int* __restrict__ feat, const float* __restrict__ w,
                      float* __restrict__ out) {
    __shared__ int s_last;
    int tid = threadIdx.x, lane = tid & 31, wid = tid >> 5;
    int r = blockIdx.x * 32 + wid;
    const int use_pc = g_use_pc;

    {
        float lse;
        int tg = g_tgt[r];
        float xt;
        if (use_pc) {
            float s = 0.f;
            #pragma unroll
            for (int q = 0; q < 4; q++) s += g_ps[(size_t)r * NTMAX + lane + 32 * q];
            #pragma unroll
            for (int o = 16; o; o >>= 1) s += __shfl_down_sync(0xffffffffu, s, o);
            lse = g_cfg.delta * 256.f + logf(s);
            int u = g_useq[r];
            int h = (lane < NW)
                  ? __popc(g_Bbits[u * NW + lane] ^ g_Bbits[tg * NW + lane]) : 0;
            #pragma unroll
            for (int o = 16; o; o >>= 1) h += __shfl_down_sync(0xffffffffu, h, o);
            xt = g_cfg.delta * (256.f - (float)h);
        } else {
            float mm = neg_inf(), ss = 0.f;
            #pragma unroll
            for (int q = 0; q < 2; q++) {
                int k = lane + 32 * q;
                float mk = g_pm[(size_t)r * NTMAX + k], sk = g_ps[(size_t)r * NTMAX + k];
                if (sk > 0.f) {
                    if (mk > mm) { ss = ss * __expf(mm - mk) + sk; mm = mk; }
                    else         { ss += sk * __expf(mk - mm); }
                }
            }
            #pragma unroll
            for (int o = 16; o; o >>= 1) {
                float mo = __shfl_down_sync(0xffffffffu, mm, o);
                float so = __shfl_down_sync(0xffffffffu, ss, o);
                if (so > 0.f) {
                    if (mo > mm) { ss = ss * __expf(mm - mo) + so; mm = mo; }
                    else         { ss += so * __expf(mo - mm); }
                }
            }
            lse = mm + logf(ss);
            int u = g_useq[r];
            float dot = 0.f;
            #pragma unroll
            for (int q = 0; q < 2; q++) {
                int f0 = q * 128 + lane * 4;
                int4 a = *(const int4*)&feat[(size_t)u  * FF + f0];
                int4 b = *(const int4*)&feat[(size_t)tg * FF + f0];
                dot += w[1 + f0 + 0] * (float)(a.x * b.x) + w[1 + f0 + 1] * (float)(a.y * b.y)
                     + w[1 + f0 + 2] * (float)(a.z * b.z) + w[1 + f0 + 3] * (float)(a.w * b.w);
            }
            #pragma unroll
            for (int o = 16; o; o >>= 1) dot += __shfl_down_sync(0xffffffffu, dot, o);
            float rb = g_cfg.w0 * (g_cfg.W - g_sfeat[u]);
            xt = g_cfg.w0x2 * dot - g_cfg.w0 * g_sfeat[tg] + rb;
        }
        if (lane == 0) g_rownll[r] = lse - xt;
    }

    __syncthreads();
    if (tid == 0) {
        __threadfence();
        int t = atomicAdd(&g_ticket, 1);
        s_last = (t == gridDim.x - 1);
    }
    __syncthreads();
    if (s_last) {
        __threadfence();
        __shared__ float red[1024];
        float v = 0.f;
        if (tid < RR)        v += g_rownll[tid];
        if (tid + 1024 < RR) v += g_rownll[tid + 1024];
        red[tid] = v;
        __syncthreads();
        #pragma unroll
        for (int s = 512; s > 0; s >>= 1) {
            if (tid < s) red[tid] += red[tid + s];
            __syncthreads();
        }
        if (tid == 0) {
            out[0] = red[0] + (float)BBATCH * logf((float)VV);
            g_ticket = 0;     // reset for next graph replay
            g_use_pc = 1;
        }
    }
}

// ---------------------------------------------------------------------------
extern "C" void kernel_launch(void* const* d_in, const int* in_sizes, int n_in,
                              void* d_out, int out_size) {
    const float* w    = 0;
    const int*   feat = 0;
    const int*   seq  = 0;
    for (int i = 0; i < n_in; i++) {
        if      (in_sizes[i] == FF + 1)        w    = (const float*)d_in[i];
        else if (in_sizes[i] == VV * FF)       feat = (const int*)d_in[i];
        else if (in_sizes[i] == BBATCH * LLEN) seq  = (const int*)d_in[i];
    }
    if (!w || !feat || !seq) {
        w    = (const float*)d_in[0];
        feat = (const int*)d_in[1];
        seq  = (const int*)d_in[2];
    }

    k_prep<<<PREPB + 1, 256>>>(feat, w, seq);
    k_main<<<dim3(PCNT, MT), 256>>>(feat, w);
    k_fin<<<63, 1024>>>(feat, w, (float*)d_out);
}

// round 11
// speedup vs baseline: 12.8192x; 1.0568x over previous
#include <cuda_runtime.h>
#include <math.h>
#include <stdint.h>

// Problem constants (V=8192, F=256, B=32, L=64)
#define VV     8192
#define FF     256
#define BBATCH 32
#define LLEN   64
#define RR     2016
#define RPAD   2048
#define BM     128
#define BN     128
#define KC     32
#define NW     8           // 256 bits = 8 x u32 words
#define NWF    3           // words in partial filter (96 bits)
#define CUTOFF 20.0f       // drop logit deficits > 20 (rel err <= 1.2e-4 worst case)
#define NT     64          // fallback n-tiles (BN=128)
#define PCN    64          // pc path: n-cols per CTA
#define PCNT   128         // pc path: n-tiles
#define NTMAX  128         // pm/ps stride
#define MT     16          // m-tiles
#define VMASK  (VV - 1)
#define PREPB  (VV / 16)   // 512 packing blocks; block PREPB = cfg + seq

struct Cfg { float w0, W, w0x2, thresh, wfc, delta; int flag, ihhi; };

__device__ Cfg      g_cfg;
__device__ int      g_use_pc = 1;   // reset by k_fin each call
__device__ int      g_ticket = 0;   // reset by k_fin each call
__device__ uint32_t g_Bbits[VV * NW];
__device__ int      g_useq[RPAD];
__device__ int      g_tgt[RPAD];
__device__ float    g_sfeat[VV];
__device__ float    g_pm[RPAD * NTMAX];
__device__ float    g_ps[RPAD * NTMAX];
__device__ float    g_rownll[RPAD];

__device__ __forceinline__ float neg_inf() { return __int_as_float(0xff800000u); }

__device__ __forceinline__ uint32_t nib_of(int4 x) {
    return (uint32_t)(x.x != 0) | ((uint32_t)(x.y != 0) << 1)
         | ((uint32_t)(x.z != 0) << 2) | ((uint32_t)(x.w != 0) << 3);
}
__device__ __forceinline__ int bin_ok(int4 x) {
    return ((x.x | x.y | x.z | x.w) & ~1) == 0 &&
           x.x >= 0 && x.y >= 0 && x.z >= 0 && x.w >= 0;
}

// ---------------------------------------------------------------------------
// PREP: grid = PREPB + 1 blocks, 256 threads.
// Blocks [0, PREPB): pack 16 vocab rows each (4x int4 loads -> MLP 4),
//                    s_feat, binarity check.
// Block PREPB:       scalar cfg + seq decode.
// ---------------------------------------------------------------------------
__global__ void k_prep(const int* __restrict__ feat, const float* __restrict__ w,
                       const int* __restrict__ seq32) {
    const int bid = blockIdx.x, tid = threadIdx.x;

    if (bid < PREPB) {
        const int grp = tid >> 6;            // 0..3
        const int t   = tid & 63;            // thread within row (4 feats each)
        const int v0  = bid * 16 + grp;      // rows v0, v0+4, v0+8, v0+12

        int4 x0 = *(const int4*)&feat[(size_t)(v0     ) * FF + t * 4];
        int4 x1 = *(const int4*)&feat[(size_t)(v0 +  4) * FF + t * 4];
        int4 x2 = *(const int4*)&feat[(size_t)(v0 +  8) * FF + t * 4];
        int4 x3 = *(const int4*)&feat[(size_t)(v0 + 12) * FF + t * 4];
        // NOTE: w+1 is only 4B-aligned -> scalar loads
        float wx = w[1 + t * 4 + 0], wy = w[1 + t * 4 + 1];
        float wz = w[1 + t * 4 + 2], ww = w[1 + t * 4 + 3];

        // --- bit packing: nibble -> OR-reduce across groups of 8 lanes ---
        uint32_t n0 = nib_of(x0) << ((t & 7) * 4);
        uint32_t n1 = nib_of(x1) << ((t & 7) * 4);
        uint32_t n2 = nib_of(x2) << ((t & 7) * 4);
        uint32_t n3 = nib_of(x3) << ((t & 7) * 4);
        #pragma unroll
        for (int o = 1; o < 8; o <<= 1) {
            n0 |= __shfl_xor_sync(0xffffffffu, n0, o);
            n1 |= __shfl_xor_sync(0xffffffffu, n1, o);
            n2 |= __shfl_xor_sync(0xffffffffu, n2, o);
            n3 |= __shfl_xor_sync(0xffffffffu, n3, o);
        }
        if ((t & 7) == 0) {
            g_Bbits[(v0     ) * NW + (t >> 3)] = n0;
            g_Bbits[(v0 +  4) * NW + (t >> 3)] = n1;
            g_Bbits[(v0 +  8) * NW + (t >> 3)] = n2;
            g_Bbits[(v0 + 12) * NW + (t >> 3)] = n3;
        }

        // --- binarity ---
        int ok = bin_ok(x0) && bin_ok(x1) && bin_ok(x2) && bin_ok(x3);
        if (!__syncthreads_and(ok)) {
            if (tid == 0) atomicAnd(&g_use_pc, 0);
        }

        // --- s_feat: weighted row sums ---
        float p0 = wx * (float)x0.x + wy * (float)x0.y + wz * (float)x0.z + ww * (float)x0.w;
        float p1 = wx * (float)x1.x + wy * (float)x1.y + wz * (float)x1.z + ww * (float)x1.w;
        float p2 = wx * (float)x2.x + wy * (float)x2.y + wz * (float)x2.z + ww * (float)x2.w;
        float p3 = wx * (float)x3.x + wy * (float)x3.y + wz * (float)x3.z + ww * (float)x3.w;
        #pragma unroll
        for (int o = 16; o; o >>= 1) {
            p0 += __shfl_down_sync(0xffffffffu, p0, o);
            p1 += __shfl_down_sync(0xffffffffu, p1, o);
            p2 += __shfl_down_sync(0xffffffffu, p2, o);
            p3 += __shfl_down_sync(0xffffffffu, p3, o);
        }
        __shared__ float sred[16][2];
        if ((t & 31) == 0) {
            int half = t >> 5;
            sred[grp     ][half] = p0;
            sred[grp +  4][half] = p1;
            sred[grp +  8][half] = p2;
            sred[grp + 12][half] = p3;
        }
        __syncthreads();
        if (tid < 16) g_sfeat[bid * 16 + tid] = sred[tid][0] + sred[tid][1];
        return;
    }

    // ------- tail block: scalar config + sequence decode -------
    {
        float wf = w[1 + tid];
        float s = wf, mn = wf, mx = wf;
        #pragma unroll
        for (int o = 16; o; o >>= 1) {
            s  += __shfl_down_sync(0xffffffffu, s, o);
            mn  = fminf(mn, __shfl_down_sync(0xffffffffu, mn, o));
            mx  = fmaxf(mx, __shfl_down_sync(0xffffffffu, mx, o));
        }
        __shared__ float ssum[8], smin[8], smax[8];
        __shared__ int s_st;
        if ((tid & 31) == 0) { ssum[tid >> 5] = s; smin[tid >> 5] = mn; smax[tid >> 5] = mx; }
        if (tid < 32) {
            int odd = seq32[2 * tid + 1];
            uint32_t nz = __ballot_sync(0xffffffffu, odd != 0);
            if (tid == 0) s_st = (nz == 0) ? 2 : 1;
        }
        __syncthreads();
        if (tid == 0) {
            float S = 0.f, MN = 3.0e38f, MX = -3.0e38f;
            #pragma unroll
            for (int i = 0; i < 8; i++) {
                S += ssum[i]; MN = fminf(MN, smin[i]); MX = fmaxf(MX, smax[i]);
            }
            float w0 = w[0];
            Cfg c;
            c.w0 = w0; c.W = S; c.w0x2 = 2.0f * w0;
            c.flag = (w0 >= 0.f && MN >= 0.f) ? 1 : 0;
            c.thresh = w0 * S - 33.0f;
            c.wfc = MN;
            c.delta = w0 * MN;
            if (c.delta > 0.f) {
                float hf = CUTOFF / c.delta;
                c.ihhi = (hf >= 256.f) ? 256 : (int)hf;
            } else {
                c.ihhi = 256;
            }
            g_cfg = c;
            atomicAnd(&g_use_pc, (MN == MX && c.flag) ? 1 : 0);
        }
        const int st = s_st;
        #pragma unroll
        for (int it = 0; it < 8; it++) {
            int r = it * 256 + tid;
            if (r < RR) {
                int b = r / (LLEN - 1), t2 = r % (LLEN - 1);
                g_useq[r] = seq32[(b * LLEN + t2) * st] & VMASK;
                g_tgt[r]  = seq32[(b * LLEN + t2 + 1) * st] & VMASK;
            } else {
                g_useq[r] = 0; g_tgt[r] = 0;
            }
        }
    }
}

// ---------------------------------------------------------------------------
// MAIN: grid (PCNT, MT), 256 threads. Union smem (32 KB).
// pc path:  3-word partial-hamming filter (96 bits; P(pass|random) ~ 1e-8)
//           + rescue completing words 3..7 + exp-table; writes ps only.
// fallback: fp32 SIMT GEMM (blocks with bx < NT) + online LSE; writes pm+ps.
// ---------------------------------------------------------------------------
__global__ __launch_bounds__(256, 4) void k_main(const int* __restrict__ feat,
                                                 const float* __restrict__ w) {
    __shared__ __align__(16) char U[32768];
    const int tid = threadIdx.x;
    const Cfg c = g_cfg;

    if (g_use_pc) {
        uint32_t (*sA)[NW] = (uint32_t(*)[NW])(U);            // 4096 B
        uint32_t (*sB)[NW] = (uint32_t(*)[NW])(U + 4096);     // 2048 B
        float* tbl         = (float*)(U + 6144);              // 1028 B
        float (*red)[8]    = (float(*)[8])(U + 7200);         // 4096 B

        const int tx = tid & 7, ty = tid >> 3;
        const int n0 = blockIdx.x * PCN, m0 = blockIdx.y * BM;
        const float delta = c.delta;
        const int   ihhi  = c.ihhi;

        tbl[tid] = __expf(-delta * (float)tid);
        if (tid == 0) tbl[256] = __expf(-delta * 256.f);

        {
            int r = tid >> 1, h = (tid & 1) << 2;
            int sw = (r >> 2) & 7;
            int u = g_useq[m0 + r];
            uint4 a = *(const uint4*)&g_Bbits[(size_t)u * NW + h];
            sA[r][(h + 0) ^ sw] = a.x; sA[r][(h + 1) ^ sw] = a.y;
            sA[r][(h + 2) ^ sw] = a.z; sA[r][(h + 3) ^ sw] = a.w;
        }
        if (tid < 128) {
            int r = tid >> 1, h = (tid & 1) << 2;
            int sw = (r >> 3) & 7;
            uint4 b = *(const uint4*)&g_Bbits[(size_t)(n0 + r) * NW + h];
            sB[r][(h + 0) ^ sw] = b.x; sB[r][(h + 1) ^ sw] = b.y;
            sB[r][(h + 2) ^ sw] = b.z; sB[r][(h + 3) ^ sw] = b.w;
        }
        __syncthreads();

        int acc[4][8];
        #pragma unroll
        for (int i = 0; i < 4; i++)
            #pragma unroll
            for (int j = 0; j < 8; j++) acc[i][j] = 0;

        const int swa = ty & 7;
        // partial hamming over words 0..NWF-1 (lower bound on total)
        #pragma unroll
        for (int wi = 0; wi < NWF; wi++) {
            uint32_t av[4], bv[8];
            #pragma unroll
            for (int i = 0; i < 4; i++) av[i] = sA[ty * 4 + i][wi ^ swa];
            #pragma unroll
            for (int j = 0; j < 8; j++) bv[j] = sB[tx * 8 + j][wi ^ tx];
            #pragma unroll
            for (int i = 0; i < 4; i++)
                #pragma unroll
                for (int j = 0; j < 8; j++)
                    acc[i][j] += __popc(av[i] ^ bv[j]);
        }

        int hmin = acc[0][0];
        #pragma unroll
        for (int i = 0; i < 4; i++)
            #pragma unroll
            for (int j = 0; j < 8; j++) hmin = min(hmin, acc[i][j]);

        float s[4] = {0.f, 0.f, 0.f, 0.f};
        if (hmin <= ihhi) {
            #pragma unroll
            for (int i = 0; i < 4; i++) {
                #pragma unroll
                for (int j = 0; j < 8; j++) {
                    if (acc[i][j] <= ihhi) {
                        int h = acc[i][j];
                        #pragma unroll
                        for (int wi = NWF; wi < 8; wi++)
                            h += __popc(sA[ty * 4 + i][wi ^ swa] ^ sB[tx * 8 + j][wi ^ tx]);
                        s[i] += tbl[h];
                    }
                }
            }
        }
        #pragma unroll
        for (int i = 0; i < 4; i++) red[ty * 4 + i][tx] = s[i];
        __syncthreads();

        if (tid < BM) {
            float ss = 0.f;
            #pragma unroll
            for (int k = 0; k < 8; k++) ss += red[tid][k];
            g_ps[(size_t)(m0 + tid) * NTMAX + blockIdx.x] = ss;
        }
        return;
    }

    // ---------------- fallback fp32 GEMM ----------------
    if (blockIdx.x >= NT) return;
    float (*As)[BM] = (float(*)[BM])(U);            // 16 KB
    float (*Bs)[BN] = (float(*)[BN])(U + 16384);    // 16 KB

    const int tx = tid & 15, ty = tid >> 4;
    const int m0 = blockIdx.y * BM, n0 = blockIdx.x * BN;
    const int ldrow = tid >> 3;
    const int ldc   = (tid & 7) << 2;

    float acc[8][8];
    #pragma unroll
    for (int i = 0; i < 8; i++)
        #pragma unroll
        for (int j = 0; j < 8; j++) acc[i][j] = 0.f;

    for (int k0 = 0; k0 < FF; k0 += KC) {
        float w0c = w[1 + k0 + ldc + 0], w1c = w[1 + k0 + ldc + 1];
        float w2c = w[1 + k0 + ldc + 2], w3c = w[1 + k0 + ldc + 3];
        #pragma unroll
        for (int q = 0; q < 4; q++) {
            int row = ldrow + q * 32;
            int ua = g_useq[m0 + row];
            int4 a = *(const int4*)&feat[(size_t)ua * FF + k0 + ldc];
            As[ldc + 0][row] = w0c * (float)a.x; As[ldc + 1][row] = w1c * (float)a.y;
            As[ldc + 2][row] = w2c * (float)a.z; As[ldc + 3][row] = w3c * (float)a.w;
            int4 b = *(const int4*)&feat[(size_t)(n0 + row) * FF + k0 + ldc];
            Bs[ldc + 0][row] = (float)b.x; Bs[ldc + 1][row] = (float)b.y;
            Bs[ldc + 2][row] = (float)b.z; Bs[ldc + 3][row] = (float)b.w;
        }
        __syncthreads();
        #pragma unroll
        for (int k = 0; k < KC; k++) {
            float4 a0 = *(const float4*)&As[k][ty * 8];
            float4 a1 = *(const float4*)&As[k][ty * 8 + 4];
            float4 b0 = *(const float4*)&Bs[k][tx * 8];
            float4 b1 = *(const float4*)&Bs[k][tx * 8 + 4];
            float av[8] = {a0.x, a0.y, a0.z, a0.w, a1.x, a1.y, a1.z, a1.w};
            float bv[8] = {b0.x, b0.y, b0.z, b0.w, b1.x, b1.y, b1.z, b1.w};
            #pragma unroll
            for (int i = 0; i < 8; i++)
                #pragma unroll
                for (int j = 0; j < 8; j++)
                    acc[i][j] = fmaf(av[i], bv[j], acc[i][j]);
        }
        __syncthreads();
    }

    float (*red_m)[16] = (float(*)[16])(U);          // reuse As/Bs region
    float (*red_s)[16] = (float(*)[16])(U + 8192);

    float sv[8];
    #pragma unroll
    for (int j = 0; j < 8; j++) sv[j] = g_sfeat[n0 + tx * 8 + j];

    #pragma unroll
    for (int i = 0; i < 8; i++) {
        int m = ty * 8 + i;
        int uu = g_useq[m0 + m];
        float rb = c.w0 * (c.W - g_sfeat[uu]);
        float mi = neg_inf(), si = 0.f;
        #pragma unroll
        for (int j = 0; j < 8; j++) {
            float x = c.w0x2 * acc[i][j] - c.w0 * sv[j] + rb;
            if (!c.flag || x > c.thresh) {
                if (x > mi) { si = si * __expf(mi - x) + 1.0f; mi = x; }
                else        { si += __expf(x - mi); }
            }
        }
        red_m[m][tx] = mi;
        red_s[m][tx] = si;
    }
    __syncthreads();

    if (tid < BM) {
        float mm = neg_inf(), ss = 0.f;
        #pragma unroll
        for (int k = 0; k < 16; k++) {
            float mk = red_m[tid][k], sk = red_s[tid][k];
            if (sk > 0.f) {
                if (mk > mm) { ss = ss * __expf(mm - mk) + sk; mm = mk; }
                else         { ss += sk * __expf(mk - mm); }
            }
        }
        g_pm[(size_t)(m0 + tid) * NTMAX + blockIdx.x] = mm;
        g_ps[(size_t)(m0 + tid) * NTMAX + blockIdx.x] = ss;
    }
}

// ---------------------------------------------------------------------------
// FIN: grid 63 x 1024 (one warp per row). Last block reduces row NLLs in
// fixed order, writes the scalar, resets globals for graph replay.
// ---------------------------------------------------------------------------
__global__ void k_fin(const int* __restrict__ feat, const float* __restrict__ w,
                      float* __restrict__ out) {
    __shared__ int s_last;
    int tid = threadIdx.x, lane = tid & 31, wid = tid >> 5;
    int r = blockIdx.x * 32 + wid;
    const int use_pc = g_use_pc;

    {
        float lse;
        int tg = g_tgt[r];
        float xt;
        if (use_pc) {
            float s = 0.f;
            #pragma unroll
            for (int q = 0; q < 4; q++) s += g_ps[(size_t)r * NTMAX + lane + 32 * q];
            #pragma unroll
            for (int o = 16; o; o >>= 1) s += __shfl_down_sync(0xffffffffu, s, o);
            lse = g_cfg.delta * 256.f + logf(s);
            int u = g_useq[r];
            int h = (lane < NW)
                  ? __popc(g_Bbits[u * NW + lane] ^ g_Bbits[tg * NW + lane]) : 0;
            #pragma unroll
            for (int o = 16; o; o >>= 1) h += __shfl_down_sync(0xffffffffu, h, o);
            xt = g_cfg.delta * (256.f - (float)h);
        } else {
            float mm = neg_inf(), ss = 0.f;
            #pragma unroll
            for (int q = 0; q < 2; q++) {
                int k = lane + 32 * q;
                float mk = g_pm[(size_t)r * NTMAX + k], sk = g_ps[(size_t)r * NTMAX + k];
                if (sk > 0.f) {
                    if (mk > mm) { ss = ss * __expf(mm - mk) + sk; mm = mk; }
                    else         { ss += sk * __expf(mk - mm); }
                }
            }
            #pragma unroll
            for (int o = 16; o; o >>= 1) {
                float mo = __shfl_down_sync(0xffffffffu, mm, o);
                float so = __shfl_down_sync(0xffffffffu, ss, o);
                if (so > 0.f) {
                    if (mo > mm) { ss = ss * __expf(mm - mo) + so; mm = mo; }
                    else         { ss += so * __expf(mo - mm); }
                }
            }
            lse = mm + logf(ss);
            int u = g_useq[r];
            float dot = 0.f;
            #pragma unroll
            for (int q = 0; q < 2; q++) {
                int f0 = q * 128 + lane * 4;
                int4 a = *(const int4*)&feat[(size_t)u  * FF + f0];
                int4 b = *(const int4*)&feat[(size_t)tg * FF + f0];
                dot += w[1 + f0 + 0] * (float)(a.x * b.x) + w[1 + f0 + 1] * (float)(a.y * b.y)
                     + w[1 + f0 + 2] * (float)(a.z * b.z) + w[1 + f0 + 3] * (float)(a.w * b.w);
            }
            #pragma unroll
            for (int o = 16; o; o >>= 1) dot += __shfl_down_sync(0xffffffffu, dot, o);
            float rb = g_cfg.w0 * (g_cfg.W - g_sfeat[u]);
            xt = g_cfg.w0x2 * dot - g_cfg.w0 * g_sfeat[tg] + rb;
        }
        if (lane == 0) g_rownll[r] = lse - xt;
    }

    __syncthreads();
    if (tid == 0) {
        __threadfence();
        int t = atomicAdd(&g_ticket, 1);
        s_last = (t == gridDim.x - 1);
    }
    __syncthreads();
    if (s_last) {
        __threadfence();
        __shared__ float red[1024];
        float v = 0.f;
        if (tid < RR)        v += g_rownll[tid];
        if (tid + 1024 < RR) v += g_rownll[tid + 1024];
        red[tid] = v;
        __syncthreads();
        #pragma unroll
        for (int s = 512; s > 0; s >>= 1) {
            if (tid < s) red[tid] += red[tid + s];
            __syncthreads();
        }
        if (tid == 0) {
            out[0] = red[0] + (float)BBATCH * logf((float)VV);
            g_ticket = 0;     // reset for next graph replay
            g_use_pc = 1;
        }
    }
}

// ---------------------------------------------------------------------------
extern "C" void kernel_launch(void* const* d_in, const int* in_sizes, int n_in,
                              void* d_out, int out_size) {
    const float* w    = 0;
    const int*   feat = 0;
    const int*   seq  = 0;
    for (int i = 0; i < n_in; i++) {
        if      (in_sizes[i] == FF + 1)        w    = (const float*)d_in[i];
        else if (in_sizes[i] == VV * FF)       feat = (const int*)d_in[i];
        else if (in_sizes[i] == BBATCH * LLEN) seq  = (const int*)d_in[i];
    }
    if (!w || !feat || !seq) {
        w    = (const float*)d_in[0];
        feat = (const int*)d_in[1];
        seq  = (const int*)d_in[2];
    }

    k_prep<<<PREPB + 1, 256>>>(feat, w, seq);
    k_main<<<dim3(PCNT, MT), 256>>>(feat, w);
    k_fin<<<63, 1024>>>(feat, w, (float*)d_out);
}

// round 12
// speedup vs baseline: 13.0614x; 1.0189x over previous
#include <cuda_runtime.h>
#include <math.h>
#include <stdint.h>

// Problem constants (V=8192, F=256, B=32, L=64)
#define VV     8192
#define FF     256
#define BBATCH 32
#define LLEN   64
#define RR     2016
#define RPAD   2048
#define BM     128
#define BN     128
#define KC     32
#define NW     8           // 256 bits = 8 x u32 words
#define NWF    2           // words in partial filter (64 bits)
#define CUTOFF 20.0f       // drop logit deficits > 20 (rel err <= 1.2e-4 worst case)
#define NT     64          // fallback n-tiles (BN=128)
#define PCN    64          // pc path: n-cols per CTA
#define PCNT   128         // pc path: n-tiles
#define NTMAX  128         // pm/ps stride
#define MT     16          // m-tiles
#define VMASK  (VV - 1)
#define PREPB  (VV / 8)    // 1024 packing blocks; block PREPB = cfg + seq

struct Cfg { float w0, W, w0x2, thresh, wfc, delta; int flag, ihhi; };

__device__ Cfg      g_cfg;
__device__ int      g_use_pc = 1;   // reset by k_fin each call
__device__ int      g_ticket = 0;   // reset by k_fin each call
__device__ uint32_t g_Bbits[VV * NW];
__device__ int      g_useq[RPAD];
__device__ int      g_tgt[RPAD];
__device__ float    g_sfeat[VV];
__device__ float    g_pm[RPAD * NTMAX];
__device__ float    g_ps[RPAD * NTMAX];
__device__ float    g_rownll[RPAD];

__device__ __forceinline__ float neg_inf() { return __int_as_float(0xff800000u); }

__device__ __forceinline__ uint32_t smem_u32(const void* p) {
    uint32_t a;
    asm("{ .reg .u64 t; cvta.to.shared.u64 t, %1; cvt.u32.u64 %0, t; }" : "=r"(a) : "l"(p));
    return a;
}
#define MBAR_INIT(mb, cnt) asm volatile("mbarrier.init.shared.b64 [%0], %1;" :: "r"(mb), "r"(cnt) : "memory")
#define MBAR_EXPECT_TX(mb, bytes) asm volatile("mbarrier.arrive.expect_tx.shared.b64 _, [%0], %1;" :: "r"(mb), "r"(bytes) : "memory")
#define MBAR_WAIT(mb, ph) do {                                                  \
    uint32_t _m = (mb), _p = (ph), _d;                                          \
    asm volatile("{\n\t.reg .pred p;\n\t"                                       \
        "mbarrier.try_wait.parity.acquire.cta.shared::cta.b64 p, [%1], %2;\n\t" \
        "selp.b32 %0, 1, 0, p;\n\t}" : "=r"(_d) : "r"(_m), "r"(_p) : "memory"); \
    if (!_d) {                                                                  \
        asm volatile("{\n\t.reg .pred P1;\n\t"                                  \
            "WL_%=:\n\t"                                                        \
            "mbarrier.try_wait.parity.acquire.cta.shared::cta.b64 P1, [%0], %1, 0x989680;\n\t" \
            "@P1 bra.uni WD_%=;\n\t bra.uni WL_%=;\n\t WD_%=:\n\t}"             \
            :: "r"(_m), "r"(_p) : "memory");                                    \
    } } while (0)
#define BULK_G2S(smem_dst, gmem_src, bytes, mb)                                 \
    asm volatile("cp.async.bulk.shared::cta.global.mbarrier::complete_tx::bytes " \
        "[%0], [%1], %2, [%3];"                                                 \
        :: "r"(smem_dst), "l"(gmem_src), "r"(bytes), "r"(mb) : "memory")

__device__ __forceinline__ uint32_t nib_of(int4 x) {
    return (uint32_t)(x.x != 0) | ((uint32_t)(x.y != 0) << 1)
         | ((uint32_t)(x.z != 0) << 2) | ((uint32_t)(x.w != 0) << 3);
}
__device__ __forceinline__ int bin_ok(int4 x) {
    return ((x.x | x.y | x.z | x.w) & ~1) == 0 &&
           x.x >= 0 && x.y >= 0 && x.z >= 0 && x.w >= 0;
}

// ---------------------------------------------------------------------------
// PREP: grid = PREPB + 1 blocks, 256 threads.
// Blocks [0, PREPB): bulk-copy 8 vocab rows (8 KB) global->smem via
//                    cp.async.bulk (TMA engine, bypasses LSU issue floor),
//                    then pack bits / s_feat / binarity from smem.
// Block PREPB:       scalar cfg + seq decode.
// ---------------------------------------------------------------------------
__global__ void k_prep(const int* __restrict__ feat, const float* __restrict__ w,
                       const int* __restrict__ seq32) {
    const int bid = blockIdx.x, tid = threadIdx.x;

    if (bid < PREPB) {
        __shared__ __align__(16) int sbuf[8 * FF];   // 8 KB
        __shared__ __align__(8) unsigned long long s_mbar;

        const uint32_t mb = smem_u32(&s_mbar);
        if (tid == 0) {
            MBAR_INIT(mb, 1);
            asm volatile("fence.proxy.async.shared::cta;" ::: "memory");
            MBAR_EXPECT_TX(mb, 8 * FF * 4);
            BULK_G2S(smem_u32(sbuf), &feat[(size_t)bid * 8 * FF], 8 * FF * 4, mb);
        }
        __syncthreads();
        MBAR_WAIT(mb, 0);

        const int grp = tid >> 6;            // 0..3
        const int t   = tid & 63;            // thread within row (4 feats each)
        const int v0  = bid * 8 + grp;       // rows v0 and v0+4

        int4 x0 = *(const int4*)&sbuf[(grp    ) * FF + t * 4];
        int4 x1 = *(const int4*)&sbuf[(grp + 4) * FF + t * 4];
        // NOTE: w+1 is only 4B-aligned -> scalar loads
        float wx = w[1 + t * 4 + 0], wy = w[1 + t * 4 + 1];
        float wz = w[1 + t * 4 + 2], ww = w[1 + t * 4 + 3];

        // --- bit packing: nibble -> OR-reduce across groups of 8 lanes ---
        uint32_t n0 = nib_of(x0) << ((t & 7) * 4);
        uint32_t n1 = nib_of(x1) << ((t & 7) * 4);
        #pragma unroll
        for (int o = 1; o < 8; o <<= 1) {
            n0 |= __shfl_xor_sync(0xffffffffu, n0, o);
            n1 |= __shfl_xor_sync(0xffffffffu, n1, o);
        }
        if ((t & 7) == 0) {
            g_Bbits[(v0    ) * NW + (t >> 3)] = n0;
            g_Bbits[(v0 + 4) * NW + (t >> 3)] = n1;
        }

        // --- binarity ---
        int ok = bin_ok(x0) && bin_ok(x1);
        if (!__syncthreads_and(ok)) {
            if (tid == 0) atomicAnd(&g_use_pc, 0);
        }

        // --- s_feat: weighted row sums ---
        float p0 = wx * (float)x0.x + wy * (float)x0.y + wz * (float)x0.z + ww * (float)x0.w;
        float p1 = wx * (float)x1.x + wy * (float)x1.y + wz * (float)x1.z + ww * (float)x1.w;
        #pragma unroll
        for (int o = 16; o; o >>= 1) {
            p0 += __shfl_down_sync(0xffffffffu, p0, o);
            p1 += __shfl_down_sync(0xffffffffu, p1, o);
        }
        __shared__ float sred[8][2];
        if ((t & 31) == 0) {
            sred[grp    ][t >> 5] = p0;
            sred[grp + 4][t >> 5] = p1;
        }
        __syncthreads();
        if (tid < 8) g_sfeat[bid * 8 + tid] = sred[tid][0] + sred[tid][1];
        return;
    }

    // ------- tail block: scalar config + sequence decode -------
    {
        float wf = w[1 + tid];
        float s = wf, mn = wf, mx = wf;
        #pragma unroll
        for (int o = 16; o; o >>= 1) {
            s  += __shfl_down_sync(0xffffffffu, s, o);
            mn  = fminf(mn, __shfl_down_sync(0xffffffffu, mn, o));
            mx  = fmaxf(mx, __shfl_down_sync(0xffffffffu, mx, o));
        }
        __shared__ float ssum[8], smin[8], smax[8];
        __shared__ int s_st;
        if ((tid & 31) == 0) { ssum[tid >> 5] = s; smin[tid >> 5] = mn; smax[tid >> 5] = mx; }
        if (tid < 32) {
            int odd = seq32[2 * tid + 1];
            uint32_t nz = __ballot_sync(0xffffffffu, odd != 0);
            if (tid == 0) s_st = (nz == 0) ? 2 : 1;
        }
        __syncthreads();
        if (tid == 0) {
            float S = 0.f, MN = 3.0e38f, MX = -3.0e38f;
            #pragma unroll
            for (int i = 0; i < 8; i++) {
                S += ssum[i]; MN = fminf(MN, smin[i]); MX = fmaxf(MX, smax[i]);
            }
            float w0 = w[0];
            Cfg c;
            c.w0 = w0; c.W = S; c.w0x2 = 2.0f * w0;
            c.flag = (w0 >= 0.f && MN >= 0.f) ? 1 : 0;
            c.thresh = w0 * S - 33.0f;
            c.wfc = MN;
            c.delta = w0 * MN;
            if (c.delta > 0.f) {
                float hf = CUTOFF / c.delta;
                c.ihhi = (hf >= 256.f) ? 256 : (int)hf;
            } else {
                c.ihhi = 256;
            }
            g_cfg = c;
            atomicAnd(&g_use_pc, (MN == MX && c.flag) ? 1 : 0);
        }
        const int st = s_st;
        #pragma unroll
        for (int it = 0; it < 8; it++) {
            int r = it * 256 + tid;
            if (r < RR) {
                int b = r / (LLEN - 1), t2 = r % (LLEN - 1);
                g_useq[r] = seq32[(b * LLEN + t2) * st] & VMASK;
                g_tgt[r]  = seq32[(b * LLEN + t2 + 1) * st] & VMASK;
            } else {
                g_useq[r] = 0; g_tgt[r] = 0;
            }
        }
    }
}

// ---------------------------------------------------------------------------
// MAIN: grid (PCNT, MT), 256 threads. Union smem (32 KB).
// pc path:  2-word partial-hamming filter (64 bits; false-pass ~2e-3)
//           + rescue completing words 2..7 + exp-table; writes ps only.
// fallback: fp32 SIMT GEMM (blocks with bx < NT) + online LSE; writes pm+ps.
// ---------------------------------------------------------------------------
__global__ __launch_bounds__(256, 4) void k_main(const int* __restrict__ feat,
                                                 const float* __restrict__ w) {
    __shared__ __align__(16) char U[32768];
    const int tid = threadIdx.x;
    const Cfg c = g_cfg;

    if (g_use_pc) {
        uint32_t (*sA)[NW] = (uint32_t(*)[NW])(U);            // 4096 B
        uint32_t (*sB)[NW] = (uint32_t(*)[NW])(U + 4096);     // 2048 B
        float* tbl         = (float*)(U + 6144);              // 1028 B
        float (*red)[8]    = (float(*)[8])(U + 7200);         // 4096 B

        const int tx = tid & 7, ty = tid >> 3;
        const int n0 = blockIdx.x * PCN, m0 = blockIdx.y * BM;
        const float delta = c.delta;
        const int   ihhi  = c.ihhi;

        tbl[tid] = __expf(-delta * (float)tid);
        if (tid == 0) tbl[256] = __expf(-delta * 256.f);

        {
            int r = tid >> 1, h = (tid & 1) << 2;
            int sw = (r >> 2) & 7;
            int u = g_useq[m0 + r];
            uint4 a = *(const uint4*)&g_Bbits[(size_t)u * NW + h];
            sA[r][(h + 0) ^ sw] = a.x; sA[r][(h + 1) ^ sw] = a.y;
            sA[r][(h + 2) ^ sw] = a.z; sA[r][(h + 3) ^ sw] = a.w;
        }
        if (tid < 128) {
            int r = tid >> 1, h = (tid & 1) << 2;
            int sw = (r >> 3) & 7;
            uint4 b = *(const uint4*)&g_Bbits[(size_t)(n0 + r) * NW + h];
            sB[r][(h + 0) ^ sw] = b.x; sB[r][(h + 1) ^ sw] = b.y;
            sB[r][(h + 2) ^ sw] = b.z; sB[r][(h + 3) ^ sw] = b.w;
        }
        __syncthreads();

        int acc[4][8];
        #pragma unroll
        for (int i = 0; i < 4; i++)
            #pragma unroll
            for (int j = 0; j < 8; j++) acc[i][j] = 0;

        const int swa = ty & 7;
        // partial hamming over words 0..NWF-1 (lower bound on total)
        #pragma unroll
        for (int wi = 0; wi < NWF; wi++) {
            uint32_t av[4], bv[8];
            #pragma unroll
            for (int i = 0; i < 4; i++) av[i] = sA[ty * 4 + i][wi ^ swa];
            #pragma unroll
            for (int j = 0; j < 8; j++) bv[j] = sB[tx * 8 + j][wi ^ tx];
            #pragma unroll
            for (int i = 0; i < 4; i++)
                #pragma unroll
                for (int j = 0; j < 8; j++)
                    acc[i][j] += __popc(av[i] ^ bv[j]);
        }

        int hmin = acc[0][0];
        #pragma unroll
        for (int i = 0; i < 4; i++)
            #pragma unroll
            for (int j = 0; j < 8; j++) hmin = min(hmin, acc[i][j]);

        float s[4] = {0.f, 0.f, 0.f, 0.f};
        if (hmin <= ihhi) {
            #pragma unroll
            for (int i = 0; i < 4; i++) {
                #pragma unroll
                for (int j = 0; j < 8; j++) {
                    if (acc[i][j] <= ihhi) {
                        int h = acc[i][j];
                        #pragma unroll
                        for (int wi = NWF; wi < 8; wi++)
                            h += __popc(sA[ty * 4 + i][wi ^ swa] ^ sB[tx * 8 + j][wi ^ tx]);
                        s[i] += tbl[h];
                    }
                }
            }
        }
        #pragma unroll
        for (int i = 0; i < 4; i++) red[ty * 4 + i][tx] = s[i];
        __syncthreads();

        if (tid < BM) {
            float ss = 0.f;
            #pragma unroll
            for (int k = 0; k < 8; k++) ss += red[tid][k];
            g_ps[(size_t)(m0 + tid) * NTMAX + blockIdx.x] = ss;
        }
        return;
    }

    // ---------------- fallback fp32 GEMM ----------------
    if (blockIdx.x >= NT) return;
    float (*As)[BM] = (float(*)[BM])(U);            // 16 KB
    float (*Bs)[BN] = (float(*)[BN])(U + 16384);    // 16 KB

    const int tx = tid & 15, ty = tid >> 4;
    const int m0 = blockIdx.y * BM, n0 = blockIdx.x * BN;
    const int ldrow = tid >> 3;
    const int ldc   = (tid & 7) << 2;

    float acc[8][8];
    #pragma unroll
    for (int i = 0; i < 8; i++)
        #pragma unroll
        for (int j = 0; j < 8; j++) acc[i][j] = 0.f;

    for (int k0 = 0; k0 < FF; k0 += KC) {
        float w0c = w[1 + k0 + ldc + 0], w1c = w[1 + k0 + ldc + 1];
        float w2c = w[1 + k0 + ldc + 2], w3c = w[1 + k0 + ldc + 3];
        #pragma unroll
        for (int q = 0; q < 4; q++) {
            int row = ldrow + q * 32;
            int ua = g_useq[m0 + row];
            int4 a = *(const int4*)&feat[(size_t)ua * FF + k0 + ldc];
            As[ldc + 0][row] = w0c * (float)a.x; As[ldc + 1][row] = w1c * (float)a.y;
            As[ldc + 2][row] = w2c * (float)a.z; As[ldc + 3][row] = w3c * (float)a.w;
            int4 b = *(const int4*)&feat[(size_t)(n0 + row) * FF + k0 + ldc];
            Bs[ldc + 0][row] = (float)b.x; Bs[ldc + 1][row] = (float)b.y;
            Bs[ldc + 2][row] = (float)b.z; Bs[ldc + 3][row] = (float)b.w;
        }
        __syncthreads();
        #pragma unroll
        for (int k = 0; k < KC; k++) {
            float4 a0 = *(const float4*)&As[k][ty * 8];
            float4 a1 = *(const float4*)&As[k][ty * 8 + 4];
            float4 b0 = *(const float4*)&Bs[k][tx * 8];
            float4 b1 = *(const float4*)&Bs[k][tx * 8 + 4];
            float av[8] = {a0.x, a0.y, a0.z, a0.w, a1.x, a1.y, a1.z, a1.w};
            float bv[8] = {b0.x, b0.y, b0.z, b0.w, b1.x, b1.y, b1.z, b1.w};
            #pragma unroll
            for (int i = 0; i < 8; i++)
                #pragma unroll
                for (int j = 0; j < 8; j++)
                    acc[i][j] = fmaf(av[i], bv[j], acc[i][j]);
        }
        __syncthreads();
    }

    float (*red_m)[16] = (float(*)[16])(U);          // reuse As/Bs region
    float (*red_s)[16] = (float(*)[16])(U + 8192);

    float sv[8];
    #pragma unroll
    for (int j = 0; j < 8; j++) sv[j] = g_sfeat[n0 + tx * 8 + j];

    #pragma unroll
    for (int i = 0; i < 8; i++) {
        int m = ty * 8 + i;
        int uu = g_useq[m0 + m];
        float rb = c.w0 * (c.W - g_sfeat[uu]);
        float mi = neg_inf(), si = 0.f;
        #pragma unroll
        for (int j = 0; j < 8; j++) {
            float x = c.w0x2 * acc[i][j] - c.w0 * sv[j] + rb;
            if (!c.flag || x > c.thresh) {
                if (x > mi) { si = si * __expf(mi - x) + 1.0f; mi = x; }
                else        { si += __expf(x - mi); }
            }
        }
        red_m[m][tx] = mi;
        red_s[m][tx] = si;
    }
    __syncthreads();

    if (tid < BM) {
        float mm = neg_inf(), ss = 0.f;
        #pragma unroll
        for (int k = 0; k < 16; k++) {
            float mk = red_m[tid][k], sk = red_s[tid][k];
            if (sk > 0.f) {
                if (mk > mm) { ss = ss * __expf(mm - mk) + sk; mm = mk; }
                else         { ss += sk * __expf(mk - mm); }
            }
        }
        g_pm[(size_t)(m0 + tid) * NTMAX + blockIdx.x] = mm;
        g_ps[(size_t)(m0 + tid) * NTMAX + blockIdx.x] = ss;
    }
}

// ---------------------------------------------------------------------------
// FIN: grid 63 x 1024 (one warp per row). Last block reduces row NLLs in
// fixed order, writes the scalar, resets globals for graph replay.
// ---------------------------------------------------------------------------
__global__ void k_fin(const int* __restrict__ feat, const float* __restrict__ w,
                      float* __restrict__ out) {
    __shared__ int s_last;
    int tid = threadIdx.x, lane = tid & 31, wid = tid >> 5;
    int r = blockIdx.x * 32 + wid;
    const int use_pc = g_use_pc;

    {
        float lse;
        int tg = g_tgt[r];
        float xt;
        if (use_pc) {
            float s = 0.f;
            #pragma unroll
            for (int q = 0; q < 4; q++) s += g_ps[(size_t)r * NTMAX + lane + 32 * q];
            #pragma unroll
            for (int o = 16; o; o >>= 1) s += __shfl_down_sync(0xffffffffu, s, o);
            lse = g_cfg.delta * 256.f + logf(s);
            int u = g_useq[r];
            int h = (lane < NW)
                  ? __popc(g_Bbits[u * NW + lane] ^ g_Bbits[tg * NW + lane]) : 0;
            #pragma unroll
            for (int o = 16; o; o >>= 1) h += __shfl_down_sync(0xffffffffu, h, o);
            xt = g_cfg.delta * (256.f - (float)h);
        } else {
            float mm = neg_inf(), ss = 0.f;
            #pragma unroll
            for (int q = 0; q < 2; q++) {
                int k = lane + 32 * q;
                float mk = g_pm[(size_t)r * NTMAX + k], sk = g_ps[(size_t)r * NTMAX + k];
                if (sk > 0.f) {
                    if (mk > mm) { ss = ss * __expf(mm - mk) + sk; mm = mk; }
                    else         { ss += sk * __expf(mk - mm); }
                }
            }
            #pragma unroll
            for (int o = 16; o; o >>= 1) {
                float mo = __shfl_down_sync(0xffffffffu, mm, o);
                float so = __shfl_down_sync(0xffffffffu, ss, o);
                if (so > 0.f) {
                    if (mo > mm) { ss = ss * __expf(mm - mo) + so; mm = mo; }
                    else         { ss += so * __expf(mo - mm); }
                }
            }
            lse = mm + logf(ss);
            int u = g_useq[r];
            float dot = 0.f;
            #pragma unroll
            for (int q = 0; q < 2; q++) {
                int f0 = q * 128 + lane * 4;
                int4 a = *(const int4*)&feat[(size_t)u  * FF + f0];
                int4 b = *(const int4*)&feat[(size_t)tg * FF + f0];
                dot += w[1 + f0 + 0] * (float)(a.x * b.x) + w[1 + f0 + 1] * (float)(a.y * b.y)
                     + w[1 + f0 + 2] * (float)(a.z * b.z) + w[1 + f0 + 3] * (float)(a.w * b.w);
            }
            #pragma unroll
            for (int o = 16; o; o >>= 1) dot += __shfl_down_sync(0xffffffffu, dot, o);
            float rb = g_cfg.w0 * (g_cfg.W - g_sfeat[u]);
            xt = g_cfg.w0x2 * dot - g_cfg.w0 * g_sfeat[tg] + rb;
        }
        if (lane == 0) g_rownll[r] = lse - xt;
    }

    __syncthreads();
    if (tid == 0) {
        __threadfence();
        int t = atomicAdd(&g_ticket, 1);
        s_last = (t == gridDim.x - 1);
    }
    __syncthreads();
    if (s_last) {
        __threadfence();
        __shared__ float red[1024];
        float v = 0.f;
        if (tid < RR)        v += g_rownll[tid];
        if (tid + 1024 < RR) v += g_rownll[tid + 1024];
        red[tid] = v;
        __syncthreads();
        #pragma unroll
        for (int s = 512; s > 0; s >>= 1) {
            if (tid < s) red[tid] += red[tid + s];
            __syncthreads();
        }
        if (tid == 0) {
            out[0] = red[0] + (float)BBATCH * logf((float)VV);
            g_ticket = 0;     // reset for next graph replay
            g_use_pc = 1;
        }
    }
}

// ---------------------------------------------------------------------------
extern "C" void kernel_launch(void* const* d_in, const int* in_sizes, int n_in,
                              void* d_out, int out_size) {
    const float* w    = 0;
    const int*   feat = 0;
    const int*   seq  = 0;
    for (int i = 0; i < n_in; i++) {
        if      (in_sizes[i] == FF + 1)        w    = (const float*)d_in[i];
        else if (in_sizes[i] == VV * FF)       feat = (const int*)d_in[i];
        else if (in_sizes[i] == BBATCH * LLEN) seq  = (const int*)d_in[i];
    }
    if (!w || !feat || !seq) {
        w    = (const float*)d_in[0];
        feat = (const int*)d_in[1];
        seq  = (const int*)d_in[2];
    }

    k_prep<<<PREPB + 1, 256>>>(feat, w, seq);
    k_main<<<dim3(PCNT, MT), 256>>>(feat, w);
    k_fin<<<63, 1024>>>(feat, w, (float*)d_out);
}